// round 4
// baseline (speedup 1.0000x reference)
#include <cuda_runtime.h>

#define BATCH  4
#define SEQQ   2048
#define SEQK   2048
#define DMODEL 512
#define NH     8
#define DHEAD  64
#define NBH    (BATCH*NH)

// ---------------- scratch (static device globals; no allocation) ----------------
__device__ float g_qp [ (size_t)NBH*SEQQ*DHEAD ];   // [B,H,S,DH] 16 MB
__device__ float g_kp [ (size_t)NBH*SEQK*DHEAD ];
__device__ float g_vp [ (size_t)NBH*SEQK*DHEAD ];
__device__ float g_ctx[ (size_t)BATCH*SEQQ*DMODEL ]; // [B,Q,D]

// =====================================================================
// SGEMM: C = A[M,512] @ W[N,512]^T   (both operands K-major, row-major)
// BM=BN=128, BK=8, 256 threads, 8x8 per-thread tile.
// PROJ=1: scatter output to [B,H,S,DH] layout. PROJ=0: plain [M,N].
// =====================================================================
template<int PROJ>
__global__ __launch_bounds__(256, 2)
void sgemm_xwt(const float* __restrict__ A, const float* __restrict__ W,
               float* __restrict__ C)
{
    __shared__ float As[8][128];
    __shared__ float Bs[8][128];

    const int tid = threadIdx.x;
    const int m0  = blockIdx.y * 128;
    const int n0  = blockIdx.x * 128;

    const int lr = tid >> 1;          // 0..127
    const int lc = (tid & 1) << 2;    // 0 or 4

    const int ty = tid >> 4;          // 0..15 (row group)
    const int tx = tid & 15;          // 0..15 (col group)

    float acc[8][8];
#pragma unroll
    for (int i = 0; i < 8; i++)
#pragma unroll
        for (int j = 0; j < 8; j++) acc[i][j] = 0.f;

    const float* Aptr = A + (size_t)(m0 + lr) * DMODEL + lc;
    const float* Wptr = W + (size_t)(n0 + lr) * DMODEL + lc;

    for (int k0 = 0; k0 < DMODEL; k0 += 8) {
        float4 a4 = *(const float4*)(Aptr + k0);
        float4 w4 = *(const float4*)(Wptr + k0);
        As[lc + 0][lr] = a4.x; As[lc + 1][lr] = a4.y;
        As[lc + 2][lr] = a4.z; As[lc + 3][lr] = a4.w;
        Bs[lc + 0][lr] = w4.x; Bs[lc + 1][lr] = w4.y;
        Bs[lc + 2][lr] = w4.z; Bs[lc + 3][lr] = w4.w;
        __syncthreads();

#pragma unroll
        for (int kk = 0; kk < 8; kk++) {
            float ra[8], rb[8];
#pragma unroll
            for (int i = 0; i < 8; i++) ra[i] = As[kk][ty * 8 + i];
#pragma unroll
            for (int j = 0; j < 8; j++) rb[j] = Bs[kk][tx * 8 + j];
#pragma unroll
            for (int i = 0; i < 8; i++)
#pragma unroll
                for (int j = 0; j < 8; j++)
                    acc[i][j] += ra[i] * rb[j];
        }
        __syncthreads();
    }

#pragma unroll
    for (int i = 0; i < 8; i++) {
        const int m = m0 + ty * 8 + i;
#pragma unroll
        for (int j = 0; j < 8; j++) {
            const int n = n0 + tx * 8 + j;
            if (PROJ) {
                // m = b*2048 + s ; n = h*64 + dh  ->  [b][h][s][dh]
                const int b = m >> 11, s = m & 2047;
                const int h = n >> 6,  dh = n & 63;
                C[((((size_t)b * NH + h) * SEQQ + s) << 6) + dh] = acc[i][j];
            } else {
                C[(size_t)m * DMODEL + n] = acc[i][j];
            }
        }
    }
}

// =====================================================================
// Flash attention (fp32, online softmax), per block: 64 queries x one (b,h).
// Key tiles of 32. Only iterates over valid keys (mask == skipped work;
// exp(-1e6 - m) == 0 exactly in fp32 so this matches the reference).
// 128 threads. smem ~42 KB (static, < 48 KB).
// =====================================================================
__global__ __launch_bounds__(128)
void flash_attn(const int* __restrict__ valid_lens, float* __restrict__ ctx)
{
    __shared__ float sQ[64][65];   // padded: conflict-free column reads
    __shared__ float sK[32][65];
    __shared__ float sV[32][68];   // +4 pad: rows stay 16B-aligned for float4
    __shared__ float sP[64][33];

    const int tid = threadIdx.x;
    const int bh  = blockIdx.y;          // 0..31
    const int b   = bh >> 3;
    const int h   = bh & 7;
    const int q0  = blockIdx.x << 6;
    const int valid = valid_lens[b];

    const float* Qb = g_qp + ((size_t)bh * SEQQ + q0) * DHEAD;
    const float* Kb = g_kp + (size_t)bh * SEQK * DHEAD;
    const float* Vb = g_vp + (size_t)bh * SEQK * DHEAD;

    // load Q tile (64x64)
    for (int i = tid; i < 64 * 16; i += 128) {
        const int r = i >> 4, c4 = (i & 15) << 2;
        float4 v = *(const float4*)(Qb + r * DHEAD + c4);
        sQ[r][c4] = v.x; sQ[r][c4+1] = v.y; sQ[r][c4+2] = v.z; sQ[r][c4+3] = v.w;
    }

    // per-thread row state (2 threads per query row, each owns 32 dh cols)
    const int r    = tid >> 1;        // 0..63
    const int half = tid & 1;
    const int co   = half << 5;       // 0 or 32

    float m_prev = -1e30f, l_run = 0.f;
    float acc[32];
#pragma unroll
    for (int j = 0; j < 32; j++) acc[j] = 0.f;

    // score-stage mapping: 16x8 thread grid, each does 4x4 of the 64x32 tile
    const int ty = tid >> 3;   // 0..15
    const int tx = tid & 7;    // 0..7

    const int nTiles = (valid + 31) >> 5;
    for (int t = 0; t < nTiles; t++) {
        const int k0 = t << 5;
        __syncthreads();   // protect sK/sV/sP from previous iteration's readers

        // load K,V tiles (32x64 each)
        for (int i = tid; i < 32 * 16; i += 128) {
            const int kr = i >> 4, c4 = (i & 15) << 2;
            float4 kv = *(const float4*)(Kb + (size_t)(k0 + kr) * DHEAD + c4);
            sK[kr][c4] = kv.x; sK[kr][c4+1] = kv.y; sK[kr][c4+2] = kv.z; sK[kr][c4+3] = kv.w;
            float4 vv = *(const float4*)(Vb + (size_t)(k0 + kr) * DHEAD + c4);
            sV[kr][c4] = vv.x; sV[kr][c4+1] = vv.y; sV[kr][c4+2] = vv.z; sV[kr][c4+3] = vv.w;
        }
        __syncthreads();

        // ---- S = Q K^T / 8, masked, into sP ----
        {
            float s[4][4];
#pragma unroll
            for (int i = 0; i < 4; i++)
#pragma unroll
                for (int j = 0; j < 4; j++) s[i][j] = 0.f;

#pragma unroll 8
            for (int d = 0; d < 64; d++) {
                float qv[4], kv[4];
#pragma unroll
                for (int i = 0; i < 4; i++) qv[i] = sQ[ty + (i << 4)][d];
#pragma unroll
                for (int j = 0; j < 4; j++) kv[j] = sK[(tx << 2) + j][d];
#pragma unroll
                for (int i = 0; i < 4; i++)
#pragma unroll
                    for (int j = 0; j < 4; j++)
                        s[i][j] += qv[i] * kv[j];
            }
            const int rem = valid - k0;   // >= 1 inside loop range
#pragma unroll
            for (int i = 0; i < 4; i++)
#pragma unroll
                for (int j = 0; j < 4; j++) {
                    const int c = (tx << 2) + j;
                    sP[ty + (i << 4)][c] = (c < rem) ? s[i][j] * 0.125f : -1e30f;
                }
        }
        __syncthreads();

        // ---- online softmax for row r (both halves compute identical stats) ----
        {
            float mt = -1e30f;
#pragma unroll 8
            for (int c = 0; c < 32; c++) mt = fmaxf(mt, sP[r][c]);
            const float m_new = fmaxf(m_prev, mt);
            const float scale = __expf(m_prev - m_new);
            float p[32], psum = 0.f;
#pragma unroll 8
            for (int c = 0; c < 32; c++) { p[c] = __expf(sP[r][c] - m_new); psum += p[c]; }
            l_run = l_run * scale + psum;
            m_prev = m_new;
#pragma unroll
            for (int j = 0; j < 32; j++) acc[j] *= scale;
            // each half writes back its 16 columns (no duplicate writes)
#pragma unroll
            for (int c = 0; c < 16; c++) sP[r][(half << 4) + c] = p[(half << 4) + c];
        }
        __syncthreads();

        // ---- O += P V  (thread owns row r, dh cols [co, co+32)) ----
#pragma unroll 4
        for (int k = 0; k < 32; k++) {
            const float p = sP[r][k];
            const float4* vr = (const float4*)&sV[k][co];
#pragma unroll
            for (int j4 = 0; j4 < 8; j4++) {
                float4 v = vr[j4];
                acc[j4 * 4 + 0] += p * v.x;
                acc[j4 * 4 + 1] += p * v.y;
                acc[j4 * 4 + 2] += p * v.z;
                acc[j4 * 4 + 3] += p * v.w;
            }
        }
    }

    // epilogue: normalize and scatter to ctx [b][q][h*64+dh]
    const float inv = 1.f / l_run;
    float* out = ctx + ((size_t)b * SEQQ + q0 + r) * DMODEL + h * DHEAD + co;
#pragma unroll
    for (int j = 0; j < 32; j++) out[j] = acc[j] * inv;
}

// =====================================================================
// launch
// =====================================================================
extern "C" void kernel_launch(void* const* d_in, const int* in_sizes, int n_in,
                              void* d_out, int out_size)
{
    const float* queries    = (const float*)d_in[0];
    const float* keys       = (const float*)d_in[1];
    const float* values     = (const float*)d_in[2];
    const int*   valid_lens = (const int*)  d_in[3];
    const float* W_q        = (const float*)d_in[4];
    const float* W_k        = (const float*)d_in[5];
    const float* W_v        = (const float*)d_in[6];
    const float* W_o        = (const float*)d_in[7];
    float*       out        = (float*)d_out;

    float *qp, *kp, *vp, *ctx;
    cudaGetSymbolAddress((void**)&qp,  g_qp);
    cudaGetSymbolAddress((void**)&kp,  g_kp);
    cudaGetSymbolAddress((void**)&vp,  g_vp);
    cudaGetSymbolAddress((void**)&ctx, g_ctx);

    dim3 gridG(DMODEL / 128, (BATCH * SEQQ) / 128);   // (4, 64)
    sgemm_xwt<1><<<gridG, 256>>>(queries, W_q, qp);
    sgemm_xwt<1><<<gridG, 256>>>(keys,    W_k, kp);
    sgemm_xwt<1><<<gridG, 256>>>(values,  W_v, vp);

    dim3 gridF(SEQQ / 64, NBH);                       // (32, 32)
    flash_attn<<<gridF, 128>>>(valid_lens, ctx);

    sgemm_xwt<0><<<gridG, 256>>>(ctx, W_o, out);
}

// round 5
// speedup vs baseline: 1.0009x; 1.0009x over previous
#include <cuda_runtime.h>

#define BATCH  4
#define SEQQ   2048
#define SEQK   2048
#define DMODEL 512
#define NH     8
#define DHEAD  64
#define NBH    (BATCH*NH)

// ---------------- scratch (static device globals; no allocation) ----------------
__device__ float g_qp [ (size_t)NBH*SEQQ*DHEAD ];   // [B,H,S,DH] 16 MB
__device__ float g_kp [ (size_t)NBH*SEQK*DHEAD ];
__device__ float g_vp [ (size_t)NBH*SEQK*DHEAD ];
__device__ float g_ctx[ (size_t)BATCH*SEQQ*DMODEL ]; // [B,Q,D]

// =====================================================================
// SGEMM: C = A[M,512] @ W[N,512]^T   (both operands K-major, row-major)
// BM=BN=128, BK=8, 256 threads, 8x8 per-thread tile.
// PROJ=1: scatter output to [B,H,S,DH] layout. PROJ=0: plain [M,N].
// =====================================================================
template<int PROJ>
__global__ __launch_bounds__(256, 2)
void sgemm_xwt(const float* __restrict__ A, const float* __restrict__ W,
               float* __restrict__ C)
{
    __shared__ float As[8][128];
    __shared__ float Bs[8][128];

    const int tid = threadIdx.x;
    const int m0  = blockIdx.y * 128;
    const int n0  = blockIdx.x * 128;

    const int lr = tid >> 1;          // 0..127
    const int lc = (tid & 1) << 2;    // 0 or 4

    const int ty = tid >> 4;          // 0..15 (row group)
    const int tx = tid & 15;          // 0..15 (col group)

    float acc[8][8];
#pragma unroll
    for (int i = 0; i < 8; i++)
#pragma unroll
        for (int j = 0; j < 8; j++) acc[i][j] = 0.f;

    const float* Aptr = A + (size_t)(m0 + lr) * DMODEL + lc;
    const float* Wptr = W + (size_t)(n0 + lr) * DMODEL + lc;

    for (int k0 = 0; k0 < DMODEL; k0 += 8) {
        float4 a4 = *(const float4*)(Aptr + k0);
        float4 w4 = *(const float4*)(Wptr + k0);
        As[lc + 0][lr] = a4.x; As[lc + 1][lr] = a4.y;
        As[lc + 2][lr] = a4.z; As[lc + 3][lr] = a4.w;
        Bs[lc + 0][lr] = w4.x; Bs[lc + 1][lr] = w4.y;
        Bs[lc + 2][lr] = w4.z; Bs[lc + 3][lr] = w4.w;
        __syncthreads();

#pragma unroll
        for (int kk = 0; kk < 8; kk++) {
            float ra[8], rb[8];
#pragma unroll
            for (int i = 0; i < 8; i++) ra[i] = As[kk][ty * 8 + i];
#pragma unroll
            for (int j = 0; j < 8; j++) rb[j] = Bs[kk][tx * 8 + j];
#pragma unroll
            for (int i = 0; i < 8; i++)
#pragma unroll
                for (int j = 0; j < 8; j++)
                    acc[i][j] += ra[i] * rb[j];
        }
        __syncthreads();
    }

#pragma unroll
    for (int i = 0; i < 8; i++) {
        const int m = m0 + ty * 8 + i;
#pragma unroll
        for (int j = 0; j < 8; j++) {
            const int n = n0 + tx * 8 + j;
            if (PROJ) {
                // m = b*2048 + s ; n = h*64 + dh  ->  [b][h][s][dh]
                const int b = m >> 11, s = m & 2047;
                const int h = n >> 6,  dh = n & 63;
                C[((((size_t)b * NH + h) * SEQQ + s) << 6) + dh] = acc[i][j];
            } else {
                C[(size_t)m * DMODEL + n] = acc[i][j];
            }
        }
    }
}

// =====================================================================
// Flash attention (fp32, online softmax), per block: 64 queries x one (b,h).
// Key tiles of 32. Only iterates over valid keys (mask == skipped work;
// exp(-1e6 - m) == 0 exactly in fp32 so this matches the reference).
// 128 threads. smem ~42 KB (static, < 48 KB).
// =====================================================================
__global__ __launch_bounds__(128)
void flash_attn(const int* __restrict__ valid_lens, float* __restrict__ ctx)
{
    __shared__ float sQ[64][65];   // padded: conflict-free column reads
    __shared__ float sK[32][65];
    __shared__ float sV[32][68];   // +4 pad: rows stay 16B-aligned for float4
    __shared__ float sP[64][33];

    const int tid = threadIdx.x;
    const int bh  = blockIdx.y;          // 0..31
    const int b   = bh >> 3;
    const int h   = bh & 7;
    const int q0  = blockIdx.x << 6;
    const int valid = valid_lens[b];

    const float* Qb = g_qp + ((size_t)bh * SEQQ + q0) * DHEAD;
    const float* Kb = g_kp + (size_t)bh * SEQK * DHEAD;
    const float* Vb = g_vp + (size_t)bh * SEQK * DHEAD;

    // load Q tile (64x64)
    for (int i = tid; i < 64 * 16; i += 128) {
        const int r = i >> 4, c4 = (i & 15) << 2;
        float4 v = *(const float4*)(Qb + r * DHEAD + c4);
        sQ[r][c4] = v.x; sQ[r][c4+1] = v.y; sQ[r][c4+2] = v.z; sQ[r][c4+3] = v.w;
    }

    // per-thread row state (2 threads per query row, each owns 32 dh cols)
    const int r    = tid >> 1;        // 0..63
    const int half = tid & 1;
    const int co   = half << 5;       // 0 or 32

    float m_prev = -1e30f, l_run = 0.f;
    float acc[32];
#pragma unroll
    for (int j = 0; j < 32; j++) acc[j] = 0.f;

    // score-stage mapping: 16x8 thread grid, each does 4x4 of the 64x32 tile
    const int ty = tid >> 3;   // 0..15
    const int tx = tid & 7;    // 0..7

    const int nTiles = (valid + 31) >> 5;
    for (int t = 0; t < nTiles; t++) {
        const int k0 = t << 5;
        __syncthreads();   // protect sK/sV/sP from previous iteration's readers

        // load K,V tiles (32x64 each)
        for (int i = tid; i < 32 * 16; i += 128) {
            const int kr = i >> 4, c4 = (i & 15) << 2;
            float4 kv = *(const float4*)(Kb + (size_t)(k0 + kr) * DHEAD + c4);
            sK[kr][c4] = kv.x; sK[kr][c4+1] = kv.y; sK[kr][c4+2] = kv.z; sK[kr][c4+3] = kv.w;
            float4 vv = *(const float4*)(Vb + (size_t)(k0 + kr) * DHEAD + c4);
            sV[kr][c4] = vv.x; sV[kr][c4+1] = vv.y; sV[kr][c4+2] = vv.z; sV[kr][c4+3] = vv.w;
        }
        __syncthreads();

        // ---- S = Q K^T / 8, masked, into sP ----
        {
            float s[4][4];
#pragma unroll
            for (int i = 0; i < 4; i++)
#pragma unroll
                for (int j = 0; j < 4; j++) s[i][j] = 0.f;

#pragma unroll 8
            for (int d = 0; d < 64; d++) {
                float qv[4], kv[4];
#pragma unroll
                for (int i = 0; i < 4; i++) qv[i] = sQ[ty + (i << 4)][d];
#pragma unroll
                for (int j = 0; j < 4; j++) kv[j] = sK[(tx << 2) + j][d];
#pragma unroll
                for (int i = 0; i < 4; i++)
#pragma unroll
                    for (int j = 0; j < 4; j++)
                        s[i][j] += qv[i] * kv[j];
            }
            const int rem = valid - k0;   // >= 1 inside loop range
#pragma unroll
            for (int i = 0; i < 4; i++)
#pragma unroll
                for (int j = 0; j < 4; j++) {
                    const int c = (tx << 2) + j;
                    sP[ty + (i << 4)][c] = (c < rem) ? s[i][j] * 0.125f : -1e30f;
                }
        }
        __syncthreads();

        // ---- online softmax for row r (both halves compute identical stats) ----
        {
            float mt = -1e30f;
#pragma unroll 8
            for (int c = 0; c < 32; c++) mt = fmaxf(mt, sP[r][c]);
            const float m_new = fmaxf(m_prev, mt);
            const float scale = __expf(m_prev - m_new);
            float p[32], psum = 0.f;
#pragma unroll 8
            for (int c = 0; c < 32; c++) { p[c] = __expf(sP[r][c] - m_new); psum += p[c]; }
            l_run = l_run * scale + psum;
            m_prev = m_new;
#pragma unroll
            for (int j = 0; j < 32; j++) acc[j] *= scale;
            // each half writes back its 16 columns (no duplicate writes)
#pragma unroll
            for (int c = 0; c < 16; c++) sP[r][(half << 4) + c] = p[(half << 4) + c];
        }
        __syncthreads();

        // ---- O += P V  (thread owns row r, dh cols [co, co+32)) ----
#pragma unroll 4
        for (int k = 0; k < 32; k++) {
            const float p = sP[r][k];
            const float4* vr = (const float4*)&sV[k][co];
#pragma unroll
            for (int j4 = 0; j4 < 8; j4++) {
                float4 v = vr[j4];
                acc[j4 * 4 + 0] += p * v.x;
                acc[j4 * 4 + 1] += p * v.y;
                acc[j4 * 4 + 2] += p * v.z;
                acc[j4 * 4 + 3] += p * v.w;
            }
        }
    }

    // epilogue: normalize and scatter to ctx [b][q][h*64+dh]
    const float inv = 1.f / l_run;
    float* out = ctx + ((size_t)b * SEQQ + q0 + r) * DMODEL + h * DHEAD + co;
#pragma unroll
    for (int j = 0; j < 32; j++) out[j] = acc[j] * inv;
}

// =====================================================================
// launch
// =====================================================================
extern "C" void kernel_launch(void* const* d_in, const int* in_sizes, int n_in,
                              void* d_out, int out_size)
{
    const float* queries    = (const float*)d_in[0];
    const float* keys       = (const float*)d_in[1];
    const float* values     = (const float*)d_in[2];
    const int*   valid_lens = (const int*)  d_in[3];
    const float* W_q        = (const float*)d_in[4];
    const float* W_k        = (const float*)d_in[5];
    const float* W_v        = (const float*)d_in[6];
    const float* W_o        = (const float*)d_in[7];
    float*       out        = (float*)d_out;

    float *qp, *kp, *vp, *ctx;
    cudaGetSymbolAddress((void**)&qp,  g_qp);
    cudaGetSymbolAddress((void**)&kp,  g_kp);
    cudaGetSymbolAddress((void**)&vp,  g_vp);
    cudaGetSymbolAddress((void**)&ctx, g_ctx);

    dim3 gridG(DMODEL / 128, (BATCH * SEQQ) / 128);   // (4, 64)
    sgemm_xwt<1><<<gridG, 256>>>(queries, W_q, qp);
    sgemm_xwt<1><<<gridG, 256>>>(keys,    W_k, kp);
    sgemm_xwt<1><<<gridG, 256>>>(values,  W_v, vp);

    dim3 gridF(SEQQ / 64, NBH);                       // (32, 32)
    flash_attn<<<gridF, 128>>>(valid_lens, ctx);

    sgemm_xwt<0><<<gridG, 256>>>(ctx, W_o, out);
}

// round 6
// speedup vs baseline: 1.0010x; 1.0001x over previous
#include <cuda_runtime.h>

#define BATCH  4
#define SEQQ   2048
#define SEQK   2048
#define DMODEL 512
#define NH     8
#define DHEAD  64
#define NBH    (BATCH*NH)

// ---------------- scratch (static device globals; no allocation) ----------------
__device__ float g_qp [ (size_t)NBH*SEQQ*DHEAD ];   // [B,H,S,DH] 16 MB
__device__ float g_kp [ (size_t)NBH*SEQK*DHEAD ];
__device__ float g_vp [ (size_t)NBH*SEQK*DHEAD ];
__device__ float g_ctx[ (size_t)BATCH*SEQQ*DMODEL ]; // [B,Q,D]

// =====================================================================
// SGEMM: C = A[M,512] @ W[N,512]^T   (both operands K-major, row-major)
// BM=BN=128, BK=8, 256 threads, 8x8 per-thread tile.
// PROJ=1: scatter output to [B,H,S,DH] layout. PROJ=0: plain [M,N].
// =====================================================================
template<int PROJ>
__global__ __launch_bounds__(256, 2)
void sgemm_xwt(const float* __restrict__ A, const float* __restrict__ W,
               float* __restrict__ C)
{
    __shared__ float As[8][128];
    __shared__ float Bs[8][128];

    const int tid = threadIdx.x;
    const int m0  = blockIdx.y * 128;
    const int n0  = blockIdx.x * 128;

    const int lr = tid >> 1;          // 0..127
    const int lc = (tid & 1) << 2;    // 0 or 4

    const int ty = tid >> 4;          // 0..15 (row group)
    const int tx = tid & 15;          // 0..15 (col group)

    float acc[8][8];
#pragma unroll
    for (int i = 0; i < 8; i++)
#pragma unroll
        for (int j = 0; j < 8; j++) acc[i][j] = 0.f;

    const float* Aptr = A + (size_t)(m0 + lr) * DMODEL + lc;
    const float* Wptr = W + (size_t)(n0 + lr) * DMODEL + lc;

    for (int k0 = 0; k0 < DMODEL; k0 += 8) {
        float4 a4 = *(const float4*)(Aptr + k0);
        float4 w4 = *(const float4*)(Wptr + k0);
        As[lc + 0][lr] = a4.x; As[lc + 1][lr] = a4.y;
        As[lc + 2][lr] = a4.z; As[lc + 3][lr] = a4.w;
        Bs[lc + 0][lr] = w4.x; Bs[lc + 1][lr] = w4.y;
        Bs[lc + 2][lr] = w4.z; Bs[lc + 3][lr] = w4.w;
        __syncthreads();

#pragma unroll
        for (int kk = 0; kk < 8; kk++) {
            float ra[8], rb[8];
#pragma unroll
            for (int i = 0; i < 8; i++) ra[i] = As[kk][ty * 8 + i];
#pragma unroll
            for (int j = 0; j < 8; j++) rb[j] = Bs[kk][tx * 8 + j];
#pragma unroll
            for (int i = 0; i < 8; i++)
#pragma unroll
                for (int j = 0; j < 8; j++)
                    acc[i][j] += ra[i] * rb[j];
        }
        __syncthreads();
    }

#pragma unroll
    for (int i = 0; i < 8; i++) {
        const int m = m0 + ty * 8 + i;
#pragma unroll
        for (int j = 0; j < 8; j++) {
            const int n = n0 + tx * 8 + j;
            if (PROJ) {
                // m = b*2048 + s ; n = h*64 + dh  ->  [b][h][s][dh]
                const int b = m >> 11, s = m & 2047;
                const int h = n >> 6,  dh = n & 63;
                C[((((size_t)b * NH + h) * SEQQ + s) << 6) + dh] = acc[i][j];
            } else {
                C[(size_t)m * DMODEL + n] = acc[i][j];
            }
        }
    }
}

// =====================================================================
// Flash attention (fp32, online softmax), per block: 64 queries x one (b,h).
// Key tiles of 32. Only iterates over valid keys (mask == skipped work;
// exp(-1e6 - m) == 0 exactly in fp32 so this matches the reference).
// 128 threads. smem ~42 KB (static, < 48 KB).
// =====================================================================
__global__ __launch_bounds__(128)
void flash_attn(const int* __restrict__ valid_lens, float* __restrict__ ctx)
{
    __shared__ float sQ[64][65];   // padded: conflict-free column reads
    __shared__ float sK[32][65];
    __shared__ float sV[32][68];   // +4 pad: rows stay 16B-aligned for float4
    __shared__ float sP[64][33];

    const int tid = threadIdx.x;
    const int bh  = blockIdx.y;          // 0..31
    const int b   = bh >> 3;
    const int h   = bh & 7;
    const int q0  = blockIdx.x << 6;
    const int valid = valid_lens[b];

    const float* Qb = g_qp + ((size_t)bh * SEQQ + q0) * DHEAD;
    const float* Kb = g_kp + (size_t)bh * SEQK * DHEAD;
    const float* Vb = g_vp + (size_t)bh * SEQK * DHEAD;

    // load Q tile (64x64)
    for (int i = tid; i < 64 * 16; i += 128) {
        const int r = i >> 4, c4 = (i & 15) << 2;
        float4 v = *(const float4*)(Qb + r * DHEAD + c4);
        sQ[r][c4] = v.x; sQ[r][c4+1] = v.y; sQ[r][c4+2] = v.z; sQ[r][c4+3] = v.w;
    }

    // per-thread row state (2 threads per query row, each owns 32 dh cols)
    const int r    = tid >> 1;        // 0..63
    const int half = tid & 1;
    const int co   = half << 5;       // 0 or 32

    float m_prev = -1e30f, l_run = 0.f;
    float acc[32];
#pragma unroll
    for (int j = 0; j < 32; j++) acc[j] = 0.f;

    // score-stage mapping: 16x8 thread grid, each does 4x4 of the 64x32 tile
    const int ty = tid >> 3;   // 0..15
    const int tx = tid & 7;    // 0..7

    const int nTiles = (valid + 31) >> 5;
    for (int t = 0; t < nTiles; t++) {
        const int k0 = t << 5;
        __syncthreads();   // protect sK/sV/sP from previous iteration's readers

        // load K,V tiles (32x64 each)
        for (int i = tid; i < 32 * 16; i += 128) {
            const int kr = i >> 4, c4 = (i & 15) << 2;
            float4 kv = *(const float4*)(Kb + (size_t)(k0 + kr) * DHEAD + c4);
            sK[kr][c4] = kv.x; sK[kr][c4+1] = kv.y; sK[kr][c4+2] = kv.z; sK[kr][c4+3] = kv.w;
            float4 vv = *(const float4*)(Vb + (size_t)(k0 + kr) * DHEAD + c4);
            sV[kr][c4] = vv.x; sV[kr][c4+1] = vv.y; sV[kr][c4+2] = vv.z; sV[kr][c4+3] = vv.w;
        }
        __syncthreads();

        // ---- S = Q K^T / 8, masked, into sP ----
        {
            float s[4][4];
#pragma unroll
            for (int i = 0; i < 4; i++)
#pragma unroll
                for (int j = 0; j < 4; j++) s[i][j] = 0.f;

#pragma unroll 8
            for (int d = 0; d < 64; d++) {
                float qv[4], kv[4];
#pragma unroll
                for (int i = 0; i < 4; i++) qv[i] = sQ[ty + (i << 4)][d];
#pragma unroll
                for (int j = 0; j < 4; j++) kv[j] = sK[(tx << 2) + j][d];
#pragma unroll
                for (int i = 0; i < 4; i++)
#pragma unroll
                    for (int j = 0; j < 4; j++)
                        s[i][j] += qv[i] * kv[j];
            }
            const int rem = valid - k0;   // >= 1 inside loop range
#pragma unroll
            for (int i = 0; i < 4; i++)
#pragma unroll
                for (int j = 0; j < 4; j++) {
                    const int c = (tx << 2) + j;
                    sP[ty + (i << 4)][c] = (c < rem) ? s[i][j] * 0.125f : -1e30f;
                }
        }
        __syncthreads();

        // ---- online softmax for row r (both halves compute identical stats) ----
        {
            float mt = -1e30f;
#pragma unroll 8
            for (int c = 0; c < 32; c++) mt = fmaxf(mt, sP[r][c]);
            const float m_new = fmaxf(m_prev, mt);
            const float scale = __expf(m_prev - m_new);
            float p[32], psum = 0.f;
#pragma unroll 8
            for (int c = 0; c < 32; c++) { p[c] = __expf(sP[r][c] - m_new); psum += p[c]; }
            l_run = l_run * scale + psum;
            m_prev = m_new;
#pragma unroll
            for (int j = 0; j < 32; j++) acc[j] *= scale;
            // each half writes back its 16 columns (no duplicate writes)
#pragma unroll
            for (int c = 0; c < 16; c++) sP[r][(half << 4) + c] = p[(half << 4) + c];
        }
        __syncthreads();

        // ---- O += P V  (thread owns row r, dh cols [co, co+32)) ----
#pragma unroll 4
        for (int k = 0; k < 32; k++) {
            const float p = sP[r][k];
            const float4* vr = (const float4*)&sV[k][co];
#pragma unroll
            for (int j4 = 0; j4 < 8; j4++) {
                float4 v = vr[j4];
                acc[j4 * 4 + 0] += p * v.x;
                acc[j4 * 4 + 1] += p * v.y;
                acc[j4 * 4 + 2] += p * v.z;
                acc[j4 * 4 + 3] += p * v.w;
            }
        }
    }

    // epilogue: normalize and scatter to ctx [b][q][h*64+dh]
    const float inv = 1.f / l_run;
    float* out = ctx + ((size_t)b * SEQQ + q0 + r) * DMODEL + h * DHEAD + co;
#pragma unroll
    for (int j = 0; j < 32; j++) out[j] = acc[j] * inv;
}

// =====================================================================
// launch
// =====================================================================
extern "C" void kernel_launch(void* const* d_in, const int* in_sizes, int n_in,
                              void* d_out, int out_size)
{
    const float* queries    = (const float*)d_in[0];
    const float* keys       = (const float*)d_in[1];
    const float* values     = (const float*)d_in[2];
    const int*   valid_lens = (const int*)  d_in[3];
    const float* W_q        = (const float*)d_in[4];
    const float* W_k        = (const float*)d_in[5];
    const float* W_v        = (const float*)d_in[6];
    const float* W_o        = (const float*)d_in[7];
    float*       out        = (float*)d_out;

    float *qp, *kp, *vp, *ctx;
    cudaGetSymbolAddress((void**)&qp,  g_qp);
    cudaGetSymbolAddress((void**)&kp,  g_kp);
    cudaGetSymbolAddress((void**)&vp,  g_vp);
    cudaGetSymbolAddress((void**)&ctx, g_ctx);

    dim3 gridG(DMODEL / 128, (BATCH * SEQQ) / 128);   // (4, 64)
    sgemm_xwt<1><<<gridG, 256>>>(queries, W_q, qp);
    sgemm_xwt<1><<<gridG, 256>>>(keys,    W_k, kp);
    sgemm_xwt<1><<<gridG, 256>>>(values,  W_v, vp);

    dim3 gridF(SEQQ / 64, NBH);                       // (32, 32)
    flash_attn<<<gridF, 128>>>(valid_lens, ctx);

    sgemm_xwt<0><<<gridG, 256>>>(ctx, W_o, out);
}

// round 8
// speedup vs baseline: 1.3050x; 1.3037x over previous
#include <cuda_runtime.h>
#include <cstdint>

#define BATCH  4
#define SEQQ   2048
#define SEQK   2048
#define DMODEL 512
#define NH     8
#define DHEAD  64
#define NBH    (BATCH*NH)

// ---------------- scratch (static device globals; no allocation) ----------------
__device__ float g_qp [ (size_t)NBH*SEQQ*DHEAD ];   // [B,H,S,DH] 16 MB
__device__ float g_kp [ (size_t)NBH*SEQK*DHEAD ];
__device__ float g_vp [ (size_t)NBH*SEQK*DHEAD ];
__device__ float g_ctx[ (size_t)BATCH*SEQQ*DMODEL ]; // [B,Q,D]

// =====================================================================
// mma.sync tf32 helpers (sm_80+; works on the harness's compute_103 target)
// =====================================================================
__device__ __forceinline__ float to_tf32(float x) {
    float y;
    asm("cvt.rna.tf32.f32 %0, %1;" : "=f"(y) : "f"(x));
    return y;
}

__device__ __forceinline__ void mma_tf32_16x8x8(float* d, const uint32_t* a,
                                                const uint32_t* b) {
    asm volatile(
        "mma.sync.aligned.m16n8k8.row.col.f32.tf32.tf32.f32 "
        "{%0,%1,%2,%3}, {%4,%5,%6,%7}, {%8,%9}, {%0,%1,%2,%3};"
        : "+f"(d[0]), "+f"(d[1]), "+f"(d[2]), "+f"(d[3])
        : "r"(a[0]), "r"(a[1]), "r"(a[2]), "r"(a[3]), "r"(b[0]), "r"(b[1]));
}

// =====================================================================
// HMMA tf32 GEMM: C[M,512] = A[M,512] @ W[512,512]^T
// 128x128 block tile, 256 threads = 8 warps (2x4), warp tile 64x32.
// BK=32 single-buffered smem chunks, stride-36 rows (conflict-free frags).
// PROJ=1: scatter output to [B,H,S,DH] layout.
// =====================================================================
template<int PROJ>
__global__ __launch_bounds__(256, 2)
void gemm_mma(const float* __restrict__ A, const float* __restrict__ W,
              float* __restrict__ C)
{
    __shared__ float As[128][36];   // 18 KB
    __shared__ float Bs[128][36];   // 18 KB

    const int tid  = threadIdx.x;
    const int wid  = tid >> 5;
    const int lane = tid & 31;
    const int m0   = blockIdx.y * 128;
    const int n0   = blockIdx.x * 128;

    const int warp_m = wid >> 2;        // 0..1 -> *64 rows
    const int warp_n = wid & 3;         // 0..3 -> *32 cols
    const int g = lane >> 2;            // 0..7
    const int t = lane & 3;             // 0..3

    float acc[4][4][4];
#pragma unroll
    for (int mi = 0; mi < 4; mi++)
#pragma unroll
        for (int ni = 0; ni < 4; ni++)
#pragma unroll
            for (int f = 0; f < 4; f++) acc[mi][ni][f] = 0.f;

    for (int c = 0; c < 16; ++c) {
        const int k0 = c << 5;
        __syncthreads();    // protect smem from previous iteration's readers

        // stage A,B 128x32 chunks (tf32-rounded): 4 float4 slots per thread
#pragma unroll
        for (int s = 0; s < 4; ++s) {
            const int slot = tid + s * 256;         // 0..1023
            const int row  = slot >> 3;
            const int j    = (slot & 7) << 2;       // k offset within chunk
            float4 a4 = *(const float4*)(A + (size_t)(m0 + row) * DMODEL + k0 + j);
            As[row][j + 0] = to_tf32(a4.x); As[row][j + 1] = to_tf32(a4.y);
            As[row][j + 2] = to_tf32(a4.z); As[row][j + 3] = to_tf32(a4.w);
            float4 b4 = *(const float4*)(W + (size_t)(n0 + row) * DMODEL + k0 + j);
            Bs[row][j + 0] = to_tf32(b4.x); Bs[row][j + 1] = to_tf32(b4.y);
            Bs[row][j + 2] = to_tf32(b4.z); Bs[row][j + 3] = to_tf32(b4.w);
        }
        __syncthreads();

#pragma unroll
        for (int kk = 0; kk < 32; kk += 8) {
            uint32_t af[4][4], bf[4][2];
#pragma unroll
            for (int mi = 0; mi < 4; mi++) {
                const int rb = warp_m * 64 + mi * 16;
                af[mi][0] = __float_as_uint(As[rb + g    ][kk + t    ]);
                af[mi][1] = __float_as_uint(As[rb + g + 8][kk + t    ]);
                af[mi][2] = __float_as_uint(As[rb + g    ][kk + t + 4]);
                af[mi][3] = __float_as_uint(As[rb + g + 8][kk + t + 4]);
            }
#pragma unroll
            for (int ni = 0; ni < 4; ni++) {
                const int cb = warp_n * 32 + ni * 8;
                bf[ni][0] = __float_as_uint(Bs[cb + g][kk + t    ]);
                bf[ni][1] = __float_as_uint(Bs[cb + g][kk + t + 4]);
            }
#pragma unroll
            for (int mi = 0; mi < 4; mi++)
#pragma unroll
                for (int ni = 0; ni < 4; ni++)
                    mma_tf32_16x8x8(acc[mi][ni], af[mi], bf[ni]);
        }
    }

    // epilogue: c0/c1 at (row, col..col+1), c2/c3 at (row+8, col..col+1)
#pragma unroll
    for (int mi = 0; mi < 4; mi++) {
#pragma unroll
        for (int ni = 0; ni < 4; ni++) {
            const int row = m0 + warp_m * 64 + mi * 16 + g;
            const int col = n0 + warp_n * 32 + ni * 8 + t * 2;
            size_t o0, o1;
            if (PROJ) {
                const int b = row >> 11, s = row & 2047;
                const int h = col >> 6,  dh = col & 63;
                o0 = ((((size_t)b * NH + h) * SEQQ + s) << 6) + dh;
                o1 = o0 + (size_t)8 * (NH * SEQQ * DHEAD) / NH / SEQQ * 0; // unused
            } else {
                o0 = (size_t)row * DMODEL + col;
            }
            if (PROJ) {
                float2 v0 = make_float2(acc[mi][ni][0], acc[mi][ni][1]);
                float2 v1 = make_float2(acc[mi][ni][2], acc[mi][ni][3]);
                *(float2*)(C + o0)                 = v0;   // (row,   col)
                *(float2*)(C + o0 + ((size_t)8 << 6)) = v1; // (row+8, col): s+8 -> +8*64
            } else {
                float2 v0 = make_float2(acc[mi][ni][0], acc[mi][ni][1]);
                float2 v1 = make_float2(acc[mi][ni][2], acc[mi][ni][3]);
                *(float2*)(C + o0)                     = v0;
                *(float2*)(C + o0 + (size_t)8 * DMODEL) = v1;
            }
        }
    }
}

// =====================================================================
// Flash attention (fp32, online softmax) — unchanged passing version.
// =====================================================================
__global__ __launch_bounds__(128)
void flash_attn(const int* __restrict__ valid_lens, float* __restrict__ ctx)
{
    __shared__ float sQ[64][65];
    __shared__ float sK[32][65];
    __shared__ float sV[32][68];
    __shared__ float sP[64][33];

    const int tid = threadIdx.x;
    const int bh  = blockIdx.y;
    const int b   = bh >> 3;
    const int h   = bh & 7;
    const int q0  = blockIdx.x << 6;
    const int valid = valid_lens[b];

    const float* Qb = g_qp + ((size_t)bh * SEQQ + q0) * DHEAD;
    const float* Kb = g_kp + (size_t)bh * SEQK * DHEAD;
    const float* Vb = g_vp + (size_t)bh * SEQK * DHEAD;

    for (int i = tid; i < 64 * 16; i += 128) {
        const int r = i >> 4, c4 = (i & 15) << 2;
        float4 v = *(const float4*)(Qb + r * DHEAD + c4);
        sQ[r][c4] = v.x; sQ[r][c4+1] = v.y; sQ[r][c4+2] = v.z; sQ[r][c4+3] = v.w;
    }

    const int r    = tid >> 1;
    const int half = tid & 1;
    const int co   = half << 5;

    float m_prev = -1e30f, l_run = 0.f;
    float acc[32];
#pragma unroll
    for (int j = 0; j < 32; j++) acc[j] = 0.f;

    const int ty = tid >> 3;
    const int tx = tid & 7;

    const int nTiles = (valid + 31) >> 5;
    for (int t = 0; t < nTiles; t++) {
        const int k0 = t << 5;
        __syncthreads();

        for (int i = tid; i < 32 * 16; i += 128) {
            const int kr = i >> 4, c4 = (i & 15) << 2;
            float4 kv = *(const float4*)(Kb + (size_t)(k0 + kr) * DHEAD + c4);
            sK[kr][c4] = kv.x; sK[kr][c4+1] = kv.y; sK[kr][c4+2] = kv.z; sK[kr][c4+3] = kv.w;
            float4 vv = *(const float4*)(Vb + (size_t)(k0 + kr) * DHEAD + c4);
            sV[kr][c4] = vv.x; sV[kr][c4+1] = vv.y; sV[kr][c4+2] = vv.z; sV[kr][c4+3] = vv.w;
        }
        __syncthreads();

        {
            float s[4][4];
#pragma unroll
            for (int i = 0; i < 4; i++)
#pragma unroll
                for (int j = 0; j < 4; j++) s[i][j] = 0.f;

#pragma unroll 8
            for (int d = 0; d < 64; d++) {
                float qv[4], kv[4];
#pragma unroll
                for (int i = 0; i < 4; i++) qv[i] = sQ[ty + (i << 4)][d];
#pragma unroll
                for (int j = 0; j < 4; j++) kv[j] = sK[(tx << 2) + j][d];
#pragma unroll
                for (int i = 0; i < 4; i++)
#pragma unroll
                    for (int j = 0; j < 4; j++)
                        s[i][j] += qv[i] * kv[j];
            }
            const int rem = valid - k0;
#pragma unroll
            for (int i = 0; i < 4; i++)
#pragma unroll
                for (int j = 0; j < 4; j++) {
                    const int c = (tx << 2) + j;
                    sP[ty + (i << 4)][c] = (c < rem) ? s[i][j] * 0.125f : -1e30f;
                }
        }
        __syncthreads();

        {
            float mt = -1e30f;
#pragma unroll 8
            for (int c = 0; c < 32; c++) mt = fmaxf(mt, sP[r][c]);
            const float m_new = fmaxf(m_prev, mt);
            const float scale = __expf(m_prev - m_new);
            float p[32], psum = 0.f;
#pragma unroll 8
            for (int c = 0; c < 32; c++) { p[c] = __expf(sP[r][c] - m_new); psum += p[c]; }
            l_run = l_run * scale + psum;
            m_prev = m_new;
#pragma unroll
            for (int j = 0; j < 32; j++) acc[j] *= scale;
#pragma unroll
            for (int c = 0; c < 16; c++) sP[r][(half << 4) + c] = p[(half << 4) + c];
        }
        __syncthreads();

#pragma unroll 4
        for (int k = 0; k < 32; k++) {
            const float p = sP[r][k];
            const float4* vr = (const float4*)&sV[k][co];
#pragma unroll
            for (int j4 = 0; j4 < 8; j4++) {
                float4 v = vr[j4];
                acc[j4 * 4 + 0] += p * v.x;
                acc[j4 * 4 + 1] += p * v.y;
                acc[j4 * 4 + 2] += p * v.z;
                acc[j4 * 4 + 3] += p * v.w;
            }
        }
    }

    const float inv = 1.f / l_run;
    float* out = ctx + ((size_t)b * SEQQ + q0 + r) * DMODEL + h * DHEAD + co;
#pragma unroll
    for (int j = 0; j < 32; j++) out[j] = acc[j] * inv;
}

// =====================================================================
// launch
// =====================================================================
extern "C" void kernel_launch(void* const* d_in, const int* in_sizes, int n_in,
                              void* d_out, int out_size)
{
    const float* queries    = (const float*)d_in[0];
    const float* keys       = (const float*)d_in[1];
    const float* values     = (const float*)d_in[2];
    const int*   valid_lens = (const int*)  d_in[3];
    const float* W_q        = (const float*)d_in[4];
    const float* W_k        = (const float*)d_in[5];
    const float* W_v        = (const float*)d_in[6];
    const float* W_o        = (const float*)d_in[7];
    float*       out        = (float*)d_out;

    float *qp, *kp, *vp, *ctx;
    cudaGetSymbolAddress((void**)&qp,  g_qp);
    cudaGetSymbolAddress((void**)&kp,  g_kp);
    cudaGetSymbolAddress((void**)&vp,  g_vp);
    cudaGetSymbolAddress((void**)&ctx, g_ctx);

    dim3 gridG(DMODEL / 128, (BATCH * SEQQ) / 128);   // (4, 64)
    gemm_mma<1><<<gridG, 256>>>(queries, W_q, qp);
    gemm_mma<1><<<gridG, 256>>>(keys,    W_k, kp);
    gemm_mma<1><<<gridG, 256>>>(values,  W_v, vp);

    dim3 gridF(SEQQ / 64, NBH);                       // (32, 32)
    flash_attn<<<gridF, 128>>>(valid_lens, ctx);

    gemm_mma<0><<<gridG, 256>>>(ctx, W_o, out);
}

// round 9
// speedup vs baseline: 4.3411x; 3.3264x over previous
#include <cuda_runtime.h>
#include <cuda_fp16.h>
#include <cstdint>

#define BATCH  4
#define SEQQ   2048
#define SEQK   2048
#define DMODEL 512
#define NH     8
#define DHEAD  64
#define NBH    (BATCH*NH)

// ---------------- scratch (static device globals; no allocation) ----------------
__device__ float g_qp [ (size_t)NBH*SEQQ*DHEAD ];   // [B,H,S,DH]
__device__ float g_kp [ (size_t)NBH*SEQK*DHEAD ];
__device__ float g_vp [ (size_t)NBH*SEQK*DHEAD ];
__device__ float g_ctx[ (size_t)BATCH*SEQQ*DMODEL ]; // [B,Q,D]

// =====================================================================
// mma.sync helpers (sm_80+ path; compiles on the harness's compute_103 target)
// =====================================================================
__device__ __forceinline__ float to_tf32(float x) {
    float y;
    asm("cvt.rna.tf32.f32 %0, %1;" : "=f"(y) : "f"(x));
    return y;
}

__device__ __forceinline__ void mma_tf32_16x8x8(float* d, const uint32_t* a,
                                                const uint32_t* b) {
    asm volatile(
        "mma.sync.aligned.m16n8k8.row.col.f32.tf32.tf32.f32 "
        "{%0,%1,%2,%3}, {%4,%5,%6,%7}, {%8,%9}, {%0,%1,%2,%3};"
        : "+f"(d[0]), "+f"(d[1]), "+f"(d[2]), "+f"(d[3])
        : "r"(a[0]), "r"(a[1]), "r"(a[2]), "r"(a[3]), "r"(b[0]), "r"(b[1]));
}

__device__ __forceinline__ void mma_f16_16x8x16(float* d, const uint32_t* a,
                                                const uint32_t* b) {
    asm volatile(
        "mma.sync.aligned.m16n8k16.row.col.f32.f16.f16.f32 "
        "{%0,%1,%2,%3}, {%4,%5,%6,%7}, {%8,%9}, {%0,%1,%2,%3};"
        : "+f"(d[0]), "+f"(d[1]), "+f"(d[2]), "+f"(d[3])
        : "r"(a[0]), "r"(a[1]), "r"(a[2]), "r"(a[3]), "r"(b[0]), "r"(b[1]));
}

__device__ __forceinline__ uint32_t h2u(__half2 h) {
    return *reinterpret_cast<uint32_t*>(&h);
}

// =====================================================================
// HMMA tf32 GEMM: C[M,512] = A[M,512] @ W[512,512]^T  (unchanged, passing)
// =====================================================================
template<int PROJ>
__global__ __launch_bounds__(256, 2)
void gemm_mma(const float* __restrict__ A, const float* __restrict__ W,
              float* __restrict__ C)
{
    __shared__ float As[128][36];
    __shared__ float Bs[128][36];

    const int tid  = threadIdx.x;
    const int wid  = tid >> 5;
    const int lane = tid & 31;
    const int m0   = blockIdx.y * 128;
    const int n0   = blockIdx.x * 128;

    const int warp_m = wid >> 2;
    const int warp_n = wid & 3;
    const int g = lane >> 2;
    const int t = lane & 3;

    float acc[4][4][4];
#pragma unroll
    for (int mi = 0; mi < 4; mi++)
#pragma unroll
        for (int ni = 0; ni < 4; ni++)
#pragma unroll
            for (int f = 0; f < 4; f++) acc[mi][ni][f] = 0.f;

    for (int c = 0; c < 16; ++c) {
        const int k0 = c << 5;
        __syncthreads();
#pragma unroll
        for (int s = 0; s < 4; ++s) {
            const int slot = tid + s * 256;
            const int row  = slot >> 3;
            const int j    = (slot & 7) << 2;
            float4 a4 = *(const float4*)(A + (size_t)(m0 + row) * DMODEL + k0 + j);
            As[row][j + 0] = to_tf32(a4.x); As[row][j + 1] = to_tf32(a4.y);
            As[row][j + 2] = to_tf32(a4.z); As[row][j + 3] = to_tf32(a4.w);
            float4 b4 = *(const float4*)(W + (size_t)(n0 + row) * DMODEL + k0 + j);
            Bs[row][j + 0] = to_tf32(b4.x); Bs[row][j + 1] = to_tf32(b4.y);
            Bs[row][j + 2] = to_tf32(b4.z); Bs[row][j + 3] = to_tf32(b4.w);
        }
        __syncthreads();

#pragma unroll
        for (int kk = 0; kk < 32; kk += 8) {
            uint32_t af[4][4], bf[4][2];
#pragma unroll
            for (int mi = 0; mi < 4; mi++) {
                const int rb = warp_m * 64 + mi * 16;
                af[mi][0] = __float_as_uint(As[rb + g    ][kk + t    ]);
                af[mi][1] = __float_as_uint(As[rb + g + 8][kk + t    ]);
                af[mi][2] = __float_as_uint(As[rb + g    ][kk + t + 4]);
                af[mi][3] = __float_as_uint(As[rb + g + 8][kk + t + 4]);
            }
#pragma unroll
            for (int ni = 0; ni < 4; ni++) {
                const int cb = warp_n * 32 + ni * 8;
                bf[ni][0] = __float_as_uint(Bs[cb + g][kk + t    ]);
                bf[ni][1] = __float_as_uint(Bs[cb + g][kk + t + 4]);
            }
#pragma unroll
            for (int mi = 0; mi < 4; mi++)
#pragma unroll
                for (int ni = 0; ni < 4; ni++)
                    mma_tf32_16x8x8(acc[mi][ni], af[mi], bf[ni]);
        }
    }

#pragma unroll
    for (int mi = 0; mi < 4; mi++) {
#pragma unroll
        for (int ni = 0; ni < 4; ni++) {
            const int row = m0 + warp_m * 64 + mi * 16 + g;
            const int col = n0 + warp_n * 32 + ni * 8 + t * 2;
            float2 v0 = make_float2(acc[mi][ni][0], acc[mi][ni][1]);
            float2 v1 = make_float2(acc[mi][ni][2], acc[mi][ni][3]);
            if (PROJ) {
                const int b = row >> 11, s = row & 2047;
                const int h = col >> 6,  dh = col & 63;
                size_t o0 = ((((size_t)b * NH + h) * SEQQ + s) << 6) + dh;
                *(float2*)(C + o0)                    = v0;   // (row,   col)
                *(float2*)(C + o0 + ((size_t)8 << 6)) = v1;   // (row+8, col)
            } else {
                size_t o0 = (size_t)row * DMODEL + col;
                *(float2*)(C + o0)                      = v0;
                *(float2*)(C + o0 + (size_t)8 * DMODEL) = v1;
            }
        }
    }
}

// =====================================================================
// Flash attention, fp16 mma (FA2-style). Block: 64 queries x one (b,h),
// 4 warps x 16 rows, BK=64 key tiles, online softmax in registers.
// Q lives in registers as fp16 A-frags (pre-scaled by 1/8).
// K smem [kcol][d] fp16 (== col-major B operand), stride 72 halves.
// V smem transposed [d][k] fp16, stride 72 halves (conflict-free frag reads).
// =====================================================================
__global__ __launch_bounds__(128)
void flash_attn(const int* __restrict__ valid_lens, float* __restrict__ ctx)
{
    __shared__ __align__(16) __half sK [64][72];   // 9216 B
    __shared__ __align__(16) __half sVt[64][72];   // 9216 B

    const int tid  = threadIdx.x;
    const int wr   = tid >> 5;          // warp 0..3 -> rows wr*16..wr*16+15
    const int lane = tid & 31;
    const int g    = lane >> 2;         // 0..7
    const int t    = lane & 3;          // 0..3

    const int bh = blockIdx.y;
    const int b  = bh >> 3;
    const int h  = bh & 7;
    const int q0 = blockIdx.x << 6;
    const int valid = valid_lens[b];

    const float* Qw = g_qp + ((size_t)bh * SEQQ + q0 + wr * 16) * DHEAD;
    const float* Kb = g_kp + (size_t)bh * SEQK * DHEAD;
    const float* Vb = g_vp + (size_t)bh * SEQK * DHEAD;

    // ---- Q A-frags (fp16, prescaled): qf[j] covers d = 16j..16j+15 ----
    uint32_t qf[4][4];
#pragma unroll
    for (int j = 0; j < 4; j++) {
        float2 v;
        v = *(const float2*)(Qw + g * 64 + j * 16 + 2 * t);
        qf[j][0] = h2u(__floats2half2_rn(v.x * 0.125f, v.y * 0.125f));
        v = *(const float2*)(Qw + (g + 8) * 64 + j * 16 + 2 * t);
        qf[j][1] = h2u(__floats2half2_rn(v.x * 0.125f, v.y * 0.125f));
        v = *(const float2*)(Qw + g * 64 + j * 16 + 8 + 2 * t);
        qf[j][2] = h2u(__floats2half2_rn(v.x * 0.125f, v.y * 0.125f));
        v = *(const float2*)(Qw + (g + 8) * 64 + j * 16 + 8 + 2 * t);
        qf[j][3] = h2u(__floats2half2_rn(v.x * 0.125f, v.y * 0.125f));
    }

    // ---- running state: rows g (idx 0) and g+8 (idx 1) ----
    float m0 = -1e30f, m1 = -1e30f;
    float l0 = 0.f,    l1 = 0.f;
    float o[8][4];                       // O frags: 8 n-frags over d, C layout
#pragma unroll
    for (int nf = 0; nf < 8; nf++)
#pragma unroll
        for (int f = 0; f < 4; f++) o[nf][f] = 0.f;

    const int nTiles = (valid + 63) >> 6;
    for (int tt = 0; tt < nTiles; tt++) {
        const int kbase = tt << 6;
        __syncthreads();

        // ---- load K tile [64][64] -> sK (fp16), coalesced ----
        for (int idx = tid; idx < 64 * 16; idx += 128) {
            const int row = idx >> 4, c4 = (idx & 15) << 2;
            float4 kv = *(const float4*)(Kb + (size_t)(kbase + row) * DHEAD + c4);
            *(__half2*)&sK[row][c4]     = __floats2half2_rn(kv.x, kv.y);
            *(__half2*)&sK[row][c4 + 2] = __floats2half2_rn(kv.z, kv.w);
        }
        // ---- load V tile transposed -> sVt[d][k] (gmem read coalesced over d) ----
        for (int idx = tid; idx < 64 * 64; idx += 128) {
            const int k = idx >> 6, d = idx & 63;
            sVt[d][k] = __float2half(Vb[(size_t)(kbase + k) * DHEAD + d]);
        }
        __syncthreads();

        // ---- S = Q K^T (prescaled) : 8 n-frags (kcols) x 4 k-steps (d) ----
        float sc[8][4];
#pragma unroll
        for (int nf = 0; nf < 8; nf++)
#pragma unroll
            for (int f = 0; f < 4; f++) sc[nf][f] = 0.f;

#pragma unroll
        for (int ks = 0; ks < 4; ks++) {
#pragma unroll
            for (int nf = 0; nf < 8; nf++) {
                uint32_t bfr[2];
                bfr[0] = *(const uint32_t*)&sK[nf * 8 + g][ks * 16 + 2 * t];
                bfr[1] = *(const uint32_t*)&sK[nf * 8 + g][ks * 16 + 2 * t + 8];
                mma_f16_16x8x16(sc[nf], qf[ks], bfr);
            }
        }

        // ---- mask tail columns ----
        if (kbase + 64 > valid) {
#pragma unroll
            for (int nf = 0; nf < 8; nf++) {
                const int c0 = kbase + nf * 8 + 2 * t;
                if (c0     >= valid) { sc[nf][0] = -1e30f; sc[nf][2] = -1e30f; }
                if (c0 + 1 >= valid) { sc[nf][1] = -1e30f; sc[nf][3] = -1e30f; }
            }
        }

        // ---- online softmax ----
        float mx0 = -1e30f, mx1 = -1e30f;
#pragma unroll
        for (int nf = 0; nf < 8; nf++) {
            mx0 = fmaxf(mx0, fmaxf(sc[nf][0], sc[nf][1]));
            mx1 = fmaxf(mx1, fmaxf(sc[nf][2], sc[nf][3]));
        }
        mx0 = fmaxf(mx0, __shfl_xor_sync(0xffffffffu, mx0, 1));
        mx0 = fmaxf(mx0, __shfl_xor_sync(0xffffffffu, mx0, 2));
        mx1 = fmaxf(mx1, __shfl_xor_sync(0xffffffffu, mx1, 1));
        mx1 = fmaxf(mx1, __shfl_xor_sync(0xffffffffu, mx1, 2));

        const float m0n = fmaxf(m0, mx0);
        const float m1n = fmaxf(m1, mx1);
        const float s0  = __expf(m0 - m0n);
        const float s1  = __expf(m1 - m1n);
        m0 = m0n; m1 = m1n;

        uint32_t pf[8][2];               // P as half2: [nf][row g / row g+8]
        float l0a = 0.f, l1a = 0.f;
#pragma unroll
        for (int nf = 0; nf < 8; nf++) {
            const float p0 = __expf(sc[nf][0] - m0n);
            const float p1 = __expf(sc[nf][1] - m0n);
            const float p2 = __expf(sc[nf][2] - m1n);
            const float p3 = __expf(sc[nf][3] - m1n);
            l0a += p0 + p1;  l1a += p2 + p3;
            pf[nf][0] = h2u(__floats2half2_rn(p0, p1));
            pf[nf][1] = h2u(__floats2half2_rn(p2, p3));
        }
        l0 = l0 * s0 + l0a;
        l1 = l1 * s1 + l1a;
#pragma unroll
        for (int nf = 0; nf < 8; nf++) {
            o[nf][0] *= s0; o[nf][1] *= s0;
            o[nf][2] *= s1; o[nf][3] *= s1;
        }

        // ---- O += P V : A-frags from pf (layout-match), B-frags from sVt ----
#pragma unroll
        for (int ks = 0; ks < 4; ks++) {
            uint32_t af[4];
            af[0] = pf[2 * ks][0];
            af[1] = pf[2 * ks][1];
            af[2] = pf[2 * ks + 1][0];
            af[3] = pf[2 * ks + 1][1];
#pragma unroll
            for (int nf = 0; nf < 8; nf++) {
                uint32_t bfr[2];
                bfr[0] = *(const uint32_t*)&sVt[nf * 8 + g][ks * 16 + 2 * t];
                bfr[1] = *(const uint32_t*)&sVt[nf * 8 + g][ks * 16 + 2 * t + 8];
                mma_f16_16x8x16(o[nf], af, bfr);
            }
        }
    }

    // ---- epilogue: reduce l across t-lanes, normalize, store ----
    l0 += __shfl_xor_sync(0xffffffffu, l0, 1);
    l0 += __shfl_xor_sync(0xffffffffu, l0, 2);
    l1 += __shfl_xor_sync(0xffffffffu, l1, 1);
    l1 += __shfl_xor_sync(0xffffffffu, l1, 2);
    const float i0 = 1.f / l0;
    const float i1 = 1.f / l1;

    const int row0 = q0 + wr * 16 + g;
    float* out0 = ctx + ((size_t)b * SEQQ + row0) * DMODEL + h * DHEAD;
    float* out1 = out0 + (size_t)8 * DMODEL;     // row g+8
#pragma unroll
    for (int nf = 0; nf < 8; nf++) {
        const int col = nf * 8 + 2 * t;
        *(float2*)(out0 + col) = make_float2(o[nf][0] * i0, o[nf][1] * i0);
        *(float2*)(out1 + col) = make_float2(o[nf][2] * i1, o[nf][3] * i1);
    }
}

// =====================================================================
// launch
// =====================================================================
extern "C" void kernel_launch(void* const* d_in, const int* in_sizes, int n_in,
                              void* d_out, int out_size)
{
    const float* queries    = (const float*)d_in[0];
    const float* keys       = (const float*)d_in[1];
    const float* values     = (const float*)d_in[2];
    const int*   valid_lens = (const int*)  d_in[3];
    const float* W_q        = (const float*)d_in[4];
    const float* W_k        = (const float*)d_in[5];
    const float* W_v        = (const float*)d_in[6];
    const float* W_o        = (const float*)d_in[7];
    float*       out        = (float*)d_out;

    float *qp, *kp, *vp, *ctx;
    cudaGetSymbolAddress((void**)&qp,  g_qp);
    cudaGetSymbolAddress((void**)&kp,  g_kp);
    cudaGetSymbolAddress((void**)&vp,  g_vp);
    cudaGetSymbolAddress((void**)&ctx, g_ctx);

    dim3 gridG(DMODEL / 128, (BATCH * SEQQ) / 128);   // (4, 64)
    gemm_mma<1><<<gridG, 256>>>(queries, W_q, qp);
    gemm_mma<1><<<gridG, 256>>>(keys,    W_k, kp);
    gemm_mma<1><<<gridG, 256>>>(values,  W_v, vp);

    dim3 gridF(SEQQ / 64, NBH);                       // (32, 32)
    flash_attn<<<gridF, 128>>>(valid_lens, ctx);

    gemm_mma<0><<<gridG, 256>>>(ctx, W_o, out);
}

// round 10
// speedup vs baseline: 5.7725x; 1.3297x over previous
#include <cuda_runtime.h>
#include <cuda_fp16.h>
#include <cstdint>

#define BATCH  4
#define SEQQ   2048
#define SEQK   2048
#define DMODEL 512
#define NH     8
#define DHEAD  64
#define NBH    (BATCH*NH)

// ---------------- scratch (static device globals; no allocation) ----------------
__device__ __align__(16) __half g_qph[ (size_t)NBH*SEQQ*DHEAD ];  // [B,H,S,DH] fp16, prescaled 1/8
__device__ __align__(16) __half g_kph[ (size_t)NBH*SEQK*DHEAD ];  // fp16
__device__ __align__(16) __half g_vph[ (size_t)NBH*SEQK*DHEAD ];  // fp16
__device__ float g_ctx[ (size_t)BATCH*SEQQ*DMODEL ];              // [B,Q,D] fp32

// =====================================================================
// mma.sync helpers (sm_80+ path; compiles on the harness's compute_103 target)
// =====================================================================
__device__ __forceinline__ float to_tf32(float x) {
    float y;
    asm("cvt.rna.tf32.f32 %0, %1;" : "=f"(y) : "f"(x));
    return y;
}

__device__ __forceinline__ void mma_tf32_16x8x8(float* d, const uint32_t* a,
                                                const uint32_t* b) {
    asm volatile(
        "mma.sync.aligned.m16n8k8.row.col.f32.tf32.tf32.f32 "
        "{%0,%1,%2,%3}, {%4,%5,%6,%7}, {%8,%9}, {%0,%1,%2,%3};"
        : "+f"(d[0]), "+f"(d[1]), "+f"(d[2]), "+f"(d[3])
        : "r"(a[0]), "r"(a[1]), "r"(a[2]), "r"(a[3]), "r"(b[0]), "r"(b[1]));
}

__device__ __forceinline__ void mma_f16_16x8x16(float* d, const uint32_t* a,
                                                const uint32_t* b) {
    asm volatile(
        "mma.sync.aligned.m16n8k16.row.col.f32.f16.f16.f32 "
        "{%0,%1,%2,%3}, {%4,%5,%6,%7}, {%8,%9}, {%0,%1,%2,%3};"
        : "+f"(d[0]), "+f"(d[1]), "+f"(d[2]), "+f"(d[3])
        : "r"(a[0]), "r"(a[1]), "r"(a[2]), "r"(a[3]), "r"(b[0]), "r"(b[1]));
}

__device__ __forceinline__ void ldsm_x4(uint32_t* r, uint32_t addr) {
    asm volatile("ldmatrix.sync.aligned.m8n8.x4.shared.b16 {%0,%1,%2,%3}, [%4];"
                 : "=r"(r[0]), "=r"(r[1]), "=r"(r[2]), "=r"(r[3]) : "r"(addr));
}
__device__ __forceinline__ void ldsm_x4_trans(uint32_t* r, uint32_t addr) {
    asm volatile("ldmatrix.sync.aligned.m8n8.x4.trans.shared.b16 {%0,%1,%2,%3}, [%4];"
                 : "=r"(r[0]), "=r"(r[1]), "=r"(r[2]), "=r"(r[3]) : "r"(addr));
}

__device__ __forceinline__ uint32_t smem_u32(const void* p) {
    uint32_t a;
    asm("{ .reg .u64 t; cvta.to.shared.u64 t, %1; cvt.u32.u64 %0, t; }" : "=r"(a) : "l"(p));
    return a;
}

__device__ __forceinline__ uint32_t h2u(__half2 h) {
    return *reinterpret_cast<uint32_t*>(&h);
}

// =====================================================================
// HMMA tf32 GEMM: C[M,512] = A[M,512] @ W[512,512]^T
// HOUT=1: write __half with scale, scatter to [B,H,S,DH].
// HOUT=0: write fp32 plain [M,N].
// =====================================================================
template<int HOUT>
__global__ __launch_bounds__(256, 2)
void gemm_mma(const float* __restrict__ A, const float* __restrict__ W,
              void* __restrict__ Cv, float scale)
{
    __shared__ float As[128][36];
    __shared__ float Bs[128][36];

    const int tid  = threadIdx.x;
    const int wid  = tid >> 5;
    const int lane = tid & 31;
    const int m0   = blockIdx.y * 128;
    const int n0   = blockIdx.x * 128;

    const int warp_m = wid >> 2;
    const int warp_n = wid & 3;
    const int g = lane >> 2;
    const int t = lane & 3;

    float acc[4][4][4];
#pragma unroll
    for (int mi = 0; mi < 4; mi++)
#pragma unroll
        for (int ni = 0; ni < 4; ni++)
#pragma unroll
            for (int f = 0; f < 4; f++) acc[mi][ni][f] = 0.f;

    for (int c = 0; c < 16; ++c) {
        const int k0 = c << 5;
        __syncthreads();
#pragma unroll
        for (int s = 0; s < 4; ++s) {
            const int slot = tid + s * 256;
            const int row  = slot >> 3;
            const int j    = (slot & 7) << 2;
            float4 a4 = *(const float4*)(A + (size_t)(m0 + row) * DMODEL + k0 + j);
            As[row][j + 0] = to_tf32(a4.x); As[row][j + 1] = to_tf32(a4.y);
            As[row][j + 2] = to_tf32(a4.z); As[row][j + 3] = to_tf32(a4.w);
            float4 b4 = *(const float4*)(W + (size_t)(n0 + row) * DMODEL + k0 + j);
            Bs[row][j + 0] = to_tf32(b4.x); Bs[row][j + 1] = to_tf32(b4.y);
            Bs[row][j + 2] = to_tf32(b4.z); Bs[row][j + 3] = to_tf32(b4.w);
        }
        __syncthreads();

#pragma unroll
        for (int kk = 0; kk < 32; kk += 8) {
            uint32_t af[4][4], bf[4][2];
#pragma unroll
            for (int mi = 0; mi < 4; mi++) {
                const int rb = warp_m * 64 + mi * 16;
                af[mi][0] = __float_as_uint(As[rb + g    ][kk + t    ]);
                af[mi][1] = __float_as_uint(As[rb + g + 8][kk + t    ]);
                af[mi][2] = __float_as_uint(As[rb + g    ][kk + t + 4]);
                af[mi][3] = __float_as_uint(As[rb + g + 8][kk + t + 4]);
            }
#pragma unroll
            for (int ni = 0; ni < 4; ni++) {
                const int cb = warp_n * 32 + ni * 8;
                bf[ni][0] = __float_as_uint(Bs[cb + g][kk + t    ]);
                bf[ni][1] = __float_as_uint(Bs[cb + g][kk + t + 4]);
            }
#pragma unroll
            for (int mi = 0; mi < 4; mi++)
#pragma unroll
                for (int ni = 0; ni < 4; ni++)
                    mma_tf32_16x8x8(acc[mi][ni], af[mi], bf[ni]);
        }
    }

#pragma unroll
    for (int mi = 0; mi < 4; mi++) {
#pragma unroll
        for (int ni = 0; ni < 4; ni++) {
            const int row = m0 + warp_m * 64 + mi * 16 + g;
            const int col = n0 + warp_n * 32 + ni * 8 + t * 2;
            if (HOUT) {
                // scatter to [B,H,S,DH] as fp16 (scaled)
                __half* Ch = (__half*)Cv;
                const int b = row >> 11, s = row & 2047;
                const int hh = col >> 6, dh = col & 63;
                size_t o0 = ((((size_t)b * NH + hh) * SEQQ + s) << 6) + dh;
                *(__half2*)(Ch + o0) =
                    __floats2half2_rn(acc[mi][ni][0] * scale, acc[mi][ni][1] * scale);
                *(__half2*)(Ch + o0 + ((size_t)8 << 6)) =
                    __floats2half2_rn(acc[mi][ni][2] * scale, acc[mi][ni][3] * scale);
            } else {
                float* Cf = (float*)Cv;
                size_t o0 = (size_t)row * DMODEL + col;
                *(float2*)(Cf + o0) = make_float2(acc[mi][ni][0], acc[mi][ni][1]);
                *(float2*)(Cf + o0 + (size_t)8 * DMODEL) =
                    make_float2(acc[mi][ni][2], acc[mi][ni][3]);
            }
        }
    }
}

// =====================================================================
// Flash attention, fp16 mma + ldmatrix. Block: 128 queries x one (b,h),
// 8 warps x 16 rows, BK=64 key tiles, online softmax in registers.
// Q in registers (fp16 prescaled, direct gmem load).
// K smem [kcol][d], V smem [k][d] (natural), both SW128-swizzled 128B rows.
// K frags: ldmatrix x4; V frags: ldmatrix x4 .trans (no explicit transpose).
// =====================================================================
__global__ __launch_bounds__(256, 2)
void flash_attn(const int* __restrict__ valid_lens, float* __restrict__ ctx)
{
    __shared__ __align__(16) __half sK[64 * 64];   // 8 KB, swizzled
    __shared__ __align__(16) __half sV[64 * 64];   // 8 KB, swizzled

    const int tid  = threadIdx.x;
    const int wr   = tid >> 5;          // warp 0..7 -> rows wr*16..+15
    const int lane = tid & 31;
    const int g    = lane >> 2;         // 0..7
    const int t    = lane & 3;          // 0..3

    const int bh = blockIdx.y;
    const int b  = bh >> 3;
    const int h  = bh & 7;
    const int q0 = blockIdx.x << 7;     // BQ = 128
    const int valid = valid_lens[b];

    const __half* Qw = g_qph + ((size_t)bh * SEQQ + q0 + wr * 16) * DHEAD;
    const __half* Kb = g_kph + (size_t)bh * SEQK * DHEAD;
    const __half* Vb = g_vph + (size_t)bh * SEQK * DHEAD;

    // ---- Q A-frags (fp16 prescaled) direct from gmem ----
    uint32_t qf[4][4];
#pragma unroll
    for (int j = 0; j < 4; j++) {
        qf[j][0] = *(const uint32_t*)(Qw + (g    ) * 64 + j * 16 + 2 * t);
        qf[j][1] = *(const uint32_t*)(Qw + (g + 8) * 64 + j * 16 + 2 * t);
        qf[j][2] = *(const uint32_t*)(Qw + (g    ) * 64 + j * 16 + 8 + 2 * t);
        qf[j][3] = *(const uint32_t*)(Qw + (g + 8) * 64 + j * 16 + 8 + 2 * t);
    }

    // ---- per-lane ldmatrix address components ----
    const uint32_t skb = smem_u32(sK);
    const uint32_t svb = smem_u32(sV);
    const int m  = lane >> 3;       // matrix index 0..3
    const int r8 = lane & 7;        // row within 8x8 matrix
    const uint32_t xr = (uint32_t)r8 << 4;                 // swizzle xor
    // K x4: matrix m -> (nf = 2*nfp + (m>>1), kb = m&1)
    const uint32_t k_rowbase = skb + (uint32_t)(((m >> 1) << 3) + r8) * 128;
    const uint32_t k_cbit    = (uint32_t)(m & 1) << 4;
    // V x4 trans: matrix m -> (kb = m&1, nf = 2*nfp + (m>>1))
    const uint32_t v_rowbase = svb + (uint32_t)(((m & 1) << 3) + r8) * 128;
    const uint32_t v_cbit    = (uint32_t)(m >> 1) << 4;

    // ---- running state: rows g (idx 0/1) and g+8 (idx 2/3) ----
    float m0 = -1e30f, m1 = -1e30f;
    float l0 = 0.f,    l1 = 0.f;
    float o[8][4];
#pragma unroll
    for (int nf = 0; nf < 8; nf++)
#pragma unroll
        for (int f = 0; f < 4; f++) o[nf][f] = 0.f;

    const int nTiles = (valid + 63) >> 6;
    for (int tt = 0; tt < nTiles; tt++) {
        const int kbase = tt << 6;
        __syncthreads();

        // ---- stage K,V tiles (fp16, swizzled 16B chunks): 2 uint4 each ----
#pragma unroll
        for (int s = 0; s < 2; s++) {
            const int slot = tid + s * 256;        // 0..511
            const int k  = slot >> 3;
            const int c  = slot & 7;
            const uint32_t dst = (uint32_t)(k * 128 + (((uint32_t)c << 4) ^ ((k & 7) << 4)));
            *(uint4*)((char*)sK + dst) = *(const uint4*)(Kb + (size_t)(kbase + k) * 64 + c * 8);
            *(uint4*)((char*)sV + dst) = *(const uint4*)(Vb + (size_t)(kbase + k) * 64 + c * 8);
        }
        __syncthreads();

        // ---- S = Q K^T (prescaled) ----
        float sc[8][4];
#pragma unroll
        for (int nf = 0; nf < 8; nf++)
#pragma unroll
            for (int f = 0; f < 4; f++) sc[nf][f] = 0.f;

#pragma unroll
        for (int ks = 0; ks < 4; ks++) {
            const uint32_t koff = (((uint32_t)ks << 5) | k_cbit) ^ xr;
#pragma unroll
            for (int nfp = 0; nfp < 4; nfp++) {
                uint32_t r[4];
                ldsm_x4(r, k_rowbase + ((uint32_t)nfp << 11) + koff);
                mma_f16_16x8x16(sc[2 * nfp    ], qf[ks], r    );
                mma_f16_16x8x16(sc[2 * nfp + 1], qf[ks], r + 2);
            }
        }

        // ---- mask tail columns ----
        if (kbase + 64 > valid) {
#pragma unroll
            for (int nf = 0; nf < 8; nf++) {
                const int c0 = kbase + nf * 8 + 2 * t;
                if (c0     >= valid) { sc[nf][0] = -1e30f; sc[nf][2] = -1e30f; }
                if (c0 + 1 >= valid) { sc[nf][1] = -1e30f; sc[nf][3] = -1e30f; }
            }
        }

        // ---- online softmax ----
        float mx0 = -1e30f, mx1 = -1e30f;
#pragma unroll
        for (int nf = 0; nf < 8; nf++) {
            mx0 = fmaxf(mx0, fmaxf(sc[nf][0], sc[nf][1]));
            mx1 = fmaxf(mx1, fmaxf(sc[nf][2], sc[nf][3]));
        }
        mx0 = fmaxf(mx0, __shfl_xor_sync(0xffffffffu, mx0, 1));
        mx0 = fmaxf(mx0, __shfl_xor_sync(0xffffffffu, mx0, 2));
        mx1 = fmaxf(mx1, __shfl_xor_sync(0xffffffffu, mx1, 1));
        mx1 = fmaxf(mx1, __shfl_xor_sync(0xffffffffu, mx1, 2));

        const float m0n = fmaxf(m0, mx0);
        const float m1n = fmaxf(m1, mx1);
        const float s0  = __expf(m0 - m0n);
        const float s1  = __expf(m1 - m1n);
        m0 = m0n; m1 = m1n;

        uint32_t pf[8][2];
        float l0a = 0.f, l1a = 0.f;
#pragma unroll
        for (int nf = 0; nf < 8; nf++) {
            const float p0 = __expf(sc[nf][0] - m0n);
            const float p1 = __expf(sc[nf][1] - m0n);
            const float p2 = __expf(sc[nf][2] - m1n);
            const float p3 = __expf(sc[nf][3] - m1n);
            l0a += p0 + p1;  l1a += p2 + p3;
            pf[nf][0] = h2u(__floats2half2_rn(p0, p1));
            pf[nf][1] = h2u(__floats2half2_rn(p2, p3));
        }
        l0 = l0 * s0 + l0a;
        l1 = l1 * s1 + l1a;
#pragma unroll
        for (int nf = 0; nf < 8; nf++) {
            o[nf][0] *= s0; o[nf][1] *= s0;
            o[nf][2] *= s1; o[nf][3] *= s1;
        }

        // ---- O += P V : V frags via ldmatrix.trans on natural [k][d] ----
#pragma unroll
        for (int ks = 0; ks < 4; ks++) {
            uint32_t af[4];
            af[0] = pf[2 * ks][0];
            af[1] = pf[2 * ks][1];
            af[2] = pf[2 * ks + 1][0];
            af[3] = pf[2 * ks + 1][1];
            const uint32_t vrow = v_rowbase + ((uint32_t)ks << 11);
#pragma unroll
            for (int nfp = 0; nfp < 4; nfp++) {
                uint32_t r[4];
                ldsm_x4_trans(r, vrow + ((((uint32_t)nfp << 5) + v_cbit) ^ xr));
                mma_f16_16x8x16(o[2 * nfp    ], af, r    );
                mma_f16_16x8x16(o[2 * nfp + 1], af, r + 2);
            }
        }
    }

    // ---- epilogue: reduce l across t-lanes, normalize, store ----
    l0 += __shfl_xor_sync(0xffffffffu, l0, 1);
    l0 += __shfl_xor_sync(0xffffffffu, l0, 2);
    l1 += __shfl_xor_sync(0xffffffffu, l1, 1);
    l1 += __shfl_xor_sync(0xffffffffu, l1, 2);
    const float i0 = 1.f / l0;
    const float i1 = 1.f / l1;

    const int row0 = q0 + wr * 16 + g;
    float* out0 = ctx + ((size_t)b * SEQQ + row0) * DMODEL + h * DHEAD;
    float* out1 = out0 + (size_t)8 * DMODEL;
#pragma unroll
    for (int nf = 0; nf < 8; nf++) {
        const int col = nf * 8 + 2 * t;
        *(float2*)(out0 + col) = make_float2(o[nf][0] * i0, o[nf][1] * i0);
        *(float2*)(out1 + col) = make_float2(o[nf][2] * i1, o[nf][3] * i1);
    }
}

// =====================================================================
// launch
// =====================================================================
extern "C" void kernel_launch(void* const* d_in, const int* in_sizes, int n_in,
                              void* d_out, int out_size)
{
    const float* queries    = (const float*)d_in[0];
    const float* keys       = (const float*)d_in[1];
    const float* values     = (const float*)d_in[2];
    const int*   valid_lens = (const int*)  d_in[3];
    const float* W_q        = (const float*)d_in[4];
    const float* W_k        = (const float*)d_in[5];
    const float* W_v        = (const float*)d_in[6];
    const float* W_o        = (const float*)d_in[7];
    float*       out        = (float*)d_out;

    void *qp, *kp, *vp, *ctx;
    cudaGetSymbolAddress(&qp,  g_qph);
    cudaGetSymbolAddress(&kp,  g_kph);
    cudaGetSymbolAddress(&vp,  g_vph);
    cudaGetSymbolAddress(&ctx, g_ctx);

    dim3 gridG(DMODEL / 128, (BATCH * SEQQ) / 128);   // (4, 64)
    gemm_mma<1><<<gridG, 256>>>(queries, W_q, qp, 0.125f);  // Q prescaled 1/sqrt(64)
    gemm_mma<1><<<gridG, 256>>>(keys,    W_k, kp, 1.f);
    gemm_mma<1><<<gridG, 256>>>(values,  W_v, vp, 1.f);

    dim3 gridF(SEQQ / 128, NBH);                      // (16, 32)
    flash_attn<<<gridF, 256>>>(valid_lens, (float*)ctx);

    gemm_mma<0><<<gridG, 256>>>((const float*)ctx, W_o, d_out, 1.f);
}

// round 11
// speedup vs baseline: 5.7732x; 1.0001x over previous
#include <cuda_runtime.h>
#include <cuda_fp16.h>
#include <cstdint>

#define BATCH  4
#define SEQQ   2048
#define SEQK   2048
#define DMODEL 512
#define NH     8
#define DHEAD  64
#define NBH    (BATCH*NH)

// ---------------- scratch (static device globals; no allocation) ----------------
__device__ __align__(16) __half g_qph[ (size_t)NBH*SEQQ*DHEAD ];  // [B,H,S,DH] fp16, prescaled 1/8
__device__ __align__(16) __half g_kph[ (size_t)NBH*SEQK*DHEAD ];  // fp16
__device__ __align__(16) __half g_vph[ (size_t)NBH*SEQK*DHEAD ];  // fp16
__device__ float g_ctx[ (size_t)BATCH*SEQQ*DMODEL ];              // [B,Q,D] fp32

// =====================================================================
// mma.sync helpers (sm_80+ path; compiles on the harness's compute_103 target)
// =====================================================================
__device__ __forceinline__ float to_tf32(float x) {
    float y;
    asm("cvt.rna.tf32.f32 %0, %1;" : "=f"(y) : "f"(x));
    return y;
}

__device__ __forceinline__ void mma_tf32_16x8x8(float* d, const uint32_t* a,
                                                const uint32_t* b) {
    asm volatile(
        "mma.sync.aligned.m16n8k8.row.col.f32.tf32.tf32.f32 "
        "{%0,%1,%2,%3}, {%4,%5,%6,%7}, {%8,%9}, {%0,%1,%2,%3};"
        : "+f"(d[0]), "+f"(d[1]), "+f"(d[2]), "+f"(d[3])
        : "r"(a[0]), "r"(a[1]), "r"(a[2]), "r"(a[3]), "r"(b[0]), "r"(b[1]));
}

__device__ __forceinline__ void mma_f16_16x8x16(float* d, const uint32_t* a,
                                                const uint32_t* b) {
    asm volatile(
        "mma.sync.aligned.m16n8k16.row.col.f32.f16.f16.f32 "
        "{%0,%1,%2,%3}, {%4,%5,%6,%7}, {%8,%9}, {%0,%1,%2,%3};"
        : "+f"(d[0]), "+f"(d[1]), "+f"(d[2]), "+f"(d[3])
        : "r"(a[0]), "r"(a[1]), "r"(a[2]), "r"(a[3]), "r"(b[0]), "r"(b[1]));
}

__device__ __forceinline__ void ldsm_x4(uint32_t* r, uint32_t addr) {
    asm volatile("ldmatrix.sync.aligned.m8n8.x4.shared.b16 {%0,%1,%2,%3}, [%4];"
                 : "=r"(r[0]), "=r"(r[1]), "=r"(r[2]), "=r"(r[3]) : "r"(addr));
}
__device__ __forceinline__ void ldsm_x4_trans(uint32_t* r, uint32_t addr) {
    asm volatile("ldmatrix.sync.aligned.m8n8.x4.trans.shared.b16 {%0,%1,%2,%3}, [%4];"
                 : "=r"(r[0]), "=r"(r[1]), "=r"(r[2]), "=r"(r[3]) : "r"(addr));
}

__device__ __forceinline__ uint32_t smem_u32(const void* p) {
    uint32_t a;
    asm("{ .reg .u64 t; cvta.to.shared.u64 t, %1; cvt.u32.u64 %0, t; }" : "=r"(a) : "l"(p));
    return a;
}

__device__ __forceinline__ uint32_t h2u(__half2 h) {
    return *reinterpret_cast<uint32_t*>(&h);
}

// =====================================================================
// HMMA tf32 GEMM: C[M,512] = A[M,512] @ W[512,512]^T
// HOUT=1: write __half with scale, scatter to [B,H,S,DH].
// HOUT=0: write fp32 plain [M,N].
// =====================================================================
template<int HOUT>
__global__ __launch_bounds__(256, 2)
void gemm_mma(const float* __restrict__ A, const float* __restrict__ W,
              void* __restrict__ Cv, float scale)
{
    __shared__ float As[128][36];
    __shared__ float Bs[128][36];

    const int tid  = threadIdx.x;
    const int wid  = tid >> 5;
    const int lane = tid & 31;
    const int m0   = blockIdx.y * 128;
    const int n0   = blockIdx.x * 128;

    const int warp_m = wid >> 2;
    const int warp_n = wid & 3;
    const int g = lane >> 2;
    const int t = lane & 3;

    float acc[4][4][4];
#pragma unroll
    for (int mi = 0; mi < 4; mi++)
#pragma unroll
        for (int ni = 0; ni < 4; ni++)
#pragma unroll
            for (int f = 0; f < 4; f++) acc[mi][ni][f] = 0.f;

    for (int c = 0; c < 16; ++c) {
        const int k0 = c << 5;
        __syncthreads();
#pragma unroll
        for (int s = 0; s < 4; ++s) {
            const int slot = tid + s * 256;
            const int row  = slot >> 3;
            const int j    = (slot & 7) << 2;
            float4 a4 = *(const float4*)(A + (size_t)(m0 + row) * DMODEL + k0 + j);
            As[row][j + 0] = to_tf32(a4.x); As[row][j + 1] = to_tf32(a4.y);
            As[row][j + 2] = to_tf32(a4.z); As[row][j + 3] = to_tf32(a4.w);
            float4 b4 = *(const float4*)(W + (size_t)(n0 + row) * DMODEL + k0 + j);
            Bs[row][j + 0] = to_tf32(b4.x); Bs[row][j + 1] = to_tf32(b4.y);
            Bs[row][j + 2] = to_tf32(b4.z); Bs[row][j + 3] = to_tf32(b4.w);
        }
        __syncthreads();

#pragma unroll
        for (int kk = 0; kk < 32; kk += 8) {
            uint32_t af[4][4], bf[4][2];
#pragma unroll
            for (int mi = 0; mi < 4; mi++) {
                const int rb = warp_m * 64 + mi * 16;
                af[mi][0] = __float_as_uint(As[rb + g    ][kk + t    ]);
                af[mi][1] = __float_as_uint(As[rb + g + 8][kk + t    ]);
                af[mi][2] = __float_as_uint(As[rb + g    ][kk + t + 4]);
                af[mi][3] = __float_as_uint(As[rb + g + 8][kk + t + 4]);
            }
#pragma unroll
            for (int ni = 0; ni < 4; ni++) {
                const int cb = warp_n * 32 + ni * 8;
                bf[ni][0] = __float_as_uint(Bs[cb + g][kk + t    ]);
                bf[ni][1] = __float_as_uint(Bs[cb + g][kk + t + 4]);
            }
#pragma unroll
            for (int mi = 0; mi < 4; mi++)
#pragma unroll
                for (int ni = 0; ni < 4; ni++)
                    mma_tf32_16x8x8(acc[mi][ni], af[mi], bf[ni]);
        }
    }

#pragma unroll
    for (int mi = 0; mi < 4; mi++) {
#pragma unroll
        for (int ni = 0; ni < 4; ni++) {
            const int row = m0 + warp_m * 64 + mi * 16 + g;
            const int col = n0 + warp_n * 32 + ni * 8 + t * 2;
            if (HOUT) {
                // scatter to [B,H,S,DH] as fp16 (scaled)
                __half* Ch = (__half*)Cv;
                const int b = row >> 11, s = row & 2047;
                const int hh = col >> 6, dh = col & 63;
                size_t o0 = ((((size_t)b * NH + hh) * SEQQ + s) << 6) + dh;
                *(__half2*)(Ch + o0) =
                    __floats2half2_rn(acc[mi][ni][0] * scale, acc[mi][ni][1] * scale);
                *(__half2*)(Ch + o0 + ((size_t)8 << 6)) =
                    __floats2half2_rn(acc[mi][ni][2] * scale, acc[mi][ni][3] * scale);
            } else {
                float* Cf = (float*)Cv;
                size_t o0 = (size_t)row * DMODEL + col;
                *(float2*)(Cf + o0) = make_float2(acc[mi][ni][0], acc[mi][ni][1]);
                *(float2*)(Cf + o0 + (size_t)8 * DMODEL) =
                    make_float2(acc[mi][ni][2], acc[mi][ni][3]);
            }
        }
    }
}

// =====================================================================
// Flash attention, fp16 mma + ldmatrix. Block: 128 queries x one (b,h),
// 8 warps x 16 rows, BK=64 key tiles, online softmax in registers.
// Q in registers (fp16 prescaled, direct gmem load).
// K smem [kcol][d], V smem [k][d] (natural), both SW128-swizzled 128B rows.
// K frags: ldmatrix x4; V frags: ldmatrix x4 .trans (no explicit transpose).
// =====================================================================
__global__ __launch_bounds__(256, 2)
void flash_attn(const int* __restrict__ valid_lens, float* __restrict__ ctx)
{
    __shared__ __align__(16) __half sK[64 * 64];   // 8 KB, swizzled
    __shared__ __align__(16) __half sV[64 * 64];   // 8 KB, swizzled

    const int tid  = threadIdx.x;
    const int wr   = tid >> 5;          // warp 0..7 -> rows wr*16..+15
    const int lane = tid & 31;
    const int g    = lane >> 2;         // 0..7
    const int t    = lane & 3;          // 0..3

    const int bh = blockIdx.y;
    const int b  = bh >> 3;
    const int h  = bh & 7;
    const int q0 = blockIdx.x << 7;     // BQ = 128
    const int valid = valid_lens[b];

    const __half* Qw = g_qph + ((size_t)bh * SEQQ + q0 + wr * 16) * DHEAD;
    const __half* Kb = g_kph + (size_t)bh * SEQK * DHEAD;
    const __half* Vb = g_vph + (size_t)bh * SEQK * DHEAD;

    // ---- Q A-frags (fp16 prescaled) direct from gmem ----
    uint32_t qf[4][4];
#pragma unroll
    for (int j = 0; j < 4; j++) {
        qf[j][0] = *(const uint32_t*)(Qw + (g    ) * 64 + j * 16 + 2 * t);
        qf[j][1] = *(const uint32_t*)(Qw + (g + 8) * 64 + j * 16 + 2 * t);
        qf[j][2] = *(const uint32_t*)(Qw + (g    ) * 64 + j * 16 + 8 + 2 * t);
        qf[j][3] = *(const uint32_t*)(Qw + (g + 8) * 64 + j * 16 + 8 + 2 * t);
    }

    // ---- per-lane ldmatrix address components ----
    const uint32_t skb = smem_u32(sK);
    const uint32_t svb = smem_u32(sV);
    const int m  = lane >> 3;       // matrix index 0..3
    const int r8 = lane & 7;        // row within 8x8 matrix
    const uint32_t xr = (uint32_t)r8 << 4;                 // swizzle xor
    // K x4: matrix m -> (nf = 2*nfp + (m>>1), kb = m&1)
    const uint32_t k_rowbase = skb + (uint32_t)(((m >> 1) << 3) + r8) * 128;
    const uint32_t k_cbit    = (uint32_t)(m & 1) << 4;
    // V x4 trans: matrix m -> (kb = m&1, nf = 2*nfp + (m>>1))
    const uint32_t v_rowbase = svb + (uint32_t)(((m & 1) << 3) + r8) * 128;
    const uint32_t v_cbit    = (uint32_t)(m >> 1) << 4;

    // ---- running state: rows g (idx 0/1) and g+8 (idx 2/3) ----
    float m0 = -1e30f, m1 = -1e30f;
    float l0 = 0.f,    l1 = 0.f;
    float o[8][4];
#pragma unroll
    for (int nf = 0; nf < 8; nf++)
#pragma unroll
        for (int f = 0; f < 4; f++) o[nf][f] = 0.f;

    const int nTiles = (valid + 63) >> 6;
    for (int tt = 0; tt < nTiles; tt++) {
        const int kbase = tt << 6;
        __syncthreads();

        // ---- stage K,V tiles (fp16, swizzled 16B chunks): 2 uint4 each ----
#pragma unroll
        for (int s = 0; s < 2; s++) {
            const int slot = tid + s * 256;        // 0..511
            const int k  = slot >> 3;
            const int c  = slot & 7;
            const uint32_t dst = (uint32_t)(k * 128 + (((uint32_t)c << 4) ^ ((k & 7) << 4)));
            *(uint4*)((char*)sK + dst) = *(const uint4*)(Kb + (size_t)(kbase + k) * 64 + c * 8);
            *(uint4*)((char*)sV + dst) = *(const uint4*)(Vb + (size_t)(kbase + k) * 64 + c * 8);
        }
        __syncthreads();

        // ---- S = Q K^T (prescaled) ----
        float sc[8][4];
#pragma unroll
        for (int nf = 0; nf < 8; nf++)
#pragma unroll
            for (int f = 0; f < 4; f++) sc[nf][f] = 0.f;

#pragma unroll
        for (int ks = 0; ks < 4; ks++) {
            const uint32_t koff = (((uint32_t)ks << 5) | k_cbit) ^ xr;
#pragma unroll
            for (int nfp = 0; nfp < 4; nfp++) {
                uint32_t r[4];
                ldsm_x4(r, k_rowbase + ((uint32_t)nfp << 11) + koff);
                mma_f16_16x8x16(sc[2 * nfp    ], qf[ks], r    );
                mma_f16_16x8x16(sc[2 * nfp + 1], qf[ks], r + 2);
            }
        }

        // ---- mask tail columns ----
        if (kbase + 64 > valid) {
#pragma unroll
            for (int nf = 0; nf < 8; nf++) {
                const int c0 = kbase + nf * 8 + 2 * t;
                if (c0     >= valid) { sc[nf][0] = -1e30f; sc[nf][2] = -1e30f; }
                if (c0 + 1 >= valid) { sc[nf][1] = -1e30f; sc[nf][3] = -1e30f; }
            }
        }

        // ---- online softmax ----
        float mx0 = -1e30f, mx1 = -1e30f;
#pragma unroll
        for (int nf = 0; nf < 8; nf++) {
            mx0 = fmaxf(mx0, fmaxf(sc[nf][0], sc[nf][1]));
            mx1 = fmaxf(mx1, fmaxf(sc[nf][2], sc[nf][3]));
        }
        mx0 = fmaxf(mx0, __shfl_xor_sync(0xffffffffu, mx0, 1));
        mx0 = fmaxf(mx0, __shfl_xor_sync(0xffffffffu, mx0, 2));
        mx1 = fmaxf(mx1, __shfl_xor_sync(0xffffffffu, mx1, 1));
        mx1 = fmaxf(mx1, __shfl_xor_sync(0xffffffffu, mx1, 2));

        const float m0n = fmaxf(m0, mx0);
        const float m1n = fmaxf(m1, mx1);
        const float s0  = __expf(m0 - m0n);
        const float s1  = __expf(m1 - m1n);
        m0 = m0n; m1 = m1n;

        uint32_t pf[8][2];
        float l0a = 0.f, l1a = 0.f;
#pragma unroll
        for (int nf = 0; nf < 8; nf++) {
            const float p0 = __expf(sc[nf][0] - m0n);
            const float p1 = __expf(sc[nf][1] - m0n);
            const float p2 = __expf(sc[nf][2] - m1n);
            const float p3 = __expf(sc[nf][3] - m1n);
            l0a += p0 + p1;  l1a += p2 + p3;
            pf[nf][0] = h2u(__floats2half2_rn(p0, p1));
            pf[nf][1] = h2u(__floats2half2_rn(p2, p3));
        }
        l0 = l0 * s0 + l0a;
        l1 = l1 * s1 + l1a;
#pragma unroll
        for (int nf = 0; nf < 8; nf++) {
            o[nf][0] *= s0; o[nf][1] *= s0;
            o[nf][2] *= s1; o[nf][3] *= s1;
        }

        // ---- O += P V : V frags via ldmatrix.trans on natural [k][d] ----
#pragma unroll
        for (int ks = 0; ks < 4; ks++) {
            uint32_t af[4];
            af[0] = pf[2 * ks][0];
            af[1] = pf[2 * ks][1];
            af[2] = pf[2 * ks + 1][0];
            af[3] = pf[2 * ks + 1][1];
            const uint32_t vrow = v_rowbase + ((uint32_t)ks << 11);
#pragma unroll
            for (int nfp = 0; nfp < 4; nfp++) {
                uint32_t r[4];
                ldsm_x4_trans(r, vrow + ((((uint32_t)nfp << 5) + v_cbit) ^ xr));
                mma_f16_16x8x16(o[2 * nfp    ], af, r    );
                mma_f16_16x8x16(o[2 * nfp + 1], af, r + 2);
            }
        }
    }

    // ---- epilogue: reduce l across t-lanes, normalize, store ----
    l0 += __shfl_xor_sync(0xffffffffu, l0, 1);
    l0 += __shfl_xor_sync(0xffffffffu, l0, 2);
    l1 += __shfl_xor_sync(0xffffffffu, l1, 1);
    l1 += __shfl_xor_sync(0xffffffffu, l1, 2);
    const float i0 = 1.f / l0;
    const float i1 = 1.f / l1;

    const int row0 = q0 + wr * 16 + g;
    float* out0 = ctx + ((size_t)b * SEQQ + row0) * DMODEL + h * DHEAD;
    float* out1 = out0 + (size_t)8 * DMODEL;
#pragma unroll
    for (int nf = 0; nf < 8; nf++) {
        const int col = nf * 8 + 2 * t;
        *(float2*)(out0 + col) = make_float2(o[nf][0] * i0, o[nf][1] * i0);
        *(float2*)(out1 + col) = make_float2(o[nf][2] * i1, o[nf][3] * i1);
    }
}

// =====================================================================
// launch
// =====================================================================
extern "C" void kernel_launch(void* const* d_in, const int* in_sizes, int n_in,
                              void* d_out, int out_size)
{
    const float* queries    = (const float*)d_in[0];
    const float* keys       = (const float*)d_in[1];
    const float* values     = (const float*)d_in[2];
    const int*   valid_lens = (const int*)  d_in[3];
    const float* W_q        = (const float*)d_in[4];
    const float* W_k        = (const float*)d_in[5];
    const float* W_v        = (const float*)d_in[6];
    const float* W_o        = (const float*)d_in[7];
    float*       out        = (float*)d_out;

    void *qp, *kp, *vp, *ctx;
    cudaGetSymbolAddress(&qp,  g_qph);
    cudaGetSymbolAddress(&kp,  g_kph);
    cudaGetSymbolAddress(&vp,  g_vph);
    cudaGetSymbolAddress(&ctx, g_ctx);

    dim3 gridG(DMODEL / 128, (BATCH * SEQQ) / 128);   // (4, 64)
    gemm_mma<1><<<gridG, 256>>>(queries, W_q, qp, 0.125f);  // Q prescaled 1/sqrt(64)
    gemm_mma<1><<<gridG, 256>>>(keys,    W_k, kp, 1.f);
    gemm_mma<1><<<gridG, 256>>>(values,  W_v, vp, 1.f);

    dim3 gridF(SEQQ / 128, NBH);                      // (16, 32)
    flash_attn<<<gridF, 256>>>(valid_lens, (float*)ctx);

    gemm_mma<0><<<gridG, 256>>>((const float*)ctx, W_o, d_out, 1.f);
}

// round 12
// speedup vs baseline: 7.5257x; 1.3036x over previous
#include <cuda_runtime.h>
#include <cuda_fp16.h>
#include <cstdint>

#define BATCH  4
#define SEQQ   2048
#define SEQK   2048
#define DMODEL 512
#define NH     8
#define DHEAD  64
#define NBH    (BATCH*NH)

// ---------------- scratch (static device globals; no allocation) ----------------
__device__ __align__(16) __half g_qph[ (size_t)NBH*SEQQ*DHEAD ];  // [B,H,S,DH] fp16, prescaled 1/8
__device__ __align__(16) __half g_kph[ (size_t)NBH*SEQK*DHEAD ];  // fp16
__device__ __align__(16) __half g_vph[ (size_t)NBH*SEQK*DHEAD ];  // fp16
__device__ __align__(16) __half g_ctxh[ (size_t)BATCH*SEQQ*DMODEL ]; // [B,Q,D] fp16

// =====================================================================
// mma.sync / ldmatrix helpers (sm_80+ path; compiles on compute_103)
// =====================================================================
__device__ __forceinline__ void mma_f16_16x8x16(float* d, const uint32_t* a,
                                                const uint32_t* b) {
    asm volatile(
        "mma.sync.aligned.m16n8k16.row.col.f32.f16.f16.f32 "
        "{%0,%1,%2,%3}, {%4,%5,%6,%7}, {%8,%9}, {%0,%1,%2,%3};"
        : "+f"(d[0]), "+f"(d[1]), "+f"(d[2]), "+f"(d[3])
        : "r"(a[0]), "r"(a[1]), "r"(a[2]), "r"(a[3]), "r"(b[0]), "r"(b[1]));
}

__device__ __forceinline__ void ldsm_x4(uint32_t* r, uint32_t addr) {
    asm volatile("ldmatrix.sync.aligned.m8n8.x4.shared.b16 {%0,%1,%2,%3}, [%4];"
                 : "=r"(r[0]), "=r"(r[1]), "=r"(r[2]), "=r"(r[3]) : "r"(addr));
}
__device__ __forceinline__ void ldsm_x4_trans(uint32_t* r, uint32_t addr) {
    asm volatile("ldmatrix.sync.aligned.m8n8.x4.trans.shared.b16 {%0,%1,%2,%3}, [%4];"
                 : "=r"(r[0]), "=r"(r[1]), "=r"(r[2]), "=r"(r[3]) : "r"(addr));
}

__device__ __forceinline__ uint32_t smem_u32(const void* p) {
    uint32_t a;
    asm("{ .reg .u64 t; cvta.to.shared.u64 t, %1; cvt.u32.u64 %0, t; }" : "=r"(a) : "l"(p));
    return a;
}

__device__ __forceinline__ uint32_t h2u(__half2 h) {
    return *reinterpret_cast<uint32_t*>(&h);
}

// =====================================================================
// fp16 HMMA GEMM: C[M,512] = A[M,512] @ W[512,512]^T
// 128x128 block tile, 8 warps (2x4), warp tile 64x32, BK=64.
// SW128-swizzled fp16 smem tiles + ldmatrix fragment loads.
// AHALF: A is fp16 in gmem (uint4 staging) vs fp32 (cvt staging).
// HOUT=1: scaled fp16 scatter to [B,H,S,DH]; HOUT=0: fp32 [M,N].
// =====================================================================
template<int AHALF, int HOUT>
__global__ __launch_bounds__(256, 2)
void gemm_f16(const void* __restrict__ Av, const float* __restrict__ W,
              void* __restrict__ Cv, float scale)
{
    __shared__ __align__(16) __half sA[128 * 64];   // 16 KB
    __shared__ __align__(16) __half sB[128 * 64];   // 16 KB

    const int tid  = threadIdx.x;
    const int wid  = tid >> 5;
    const int lane = tid & 31;
    const int m0   = blockIdx.y * 128;
    const int n0   = blockIdx.x * 128;

    const int warp_m = wid >> 2;        // 0..1 -> *64 rows
    const int warp_n = wid & 3;         // 0..3 -> *32 cols
    const int g  = lane >> 2;           // 0..7  (C-frag row)
    const int t  = lane & 3;            // 0..3  (C-frag col pair)
    const int mm = lane >> 3;           // 0..3  (ldmatrix matrix idx)
    const int r8 = lane & 7;            // row within 8x8 matrix

    const uint32_t sAb = smem_u32(sA);
    const uint32_t sBb = smem_u32(sB);
    const uint32_t xr  = (uint32_t)r8 << 4;
    // A x4: m0=(rows0-7,kc0) m1=(rows8-15,kc0) m2=(rows0-7,kc1) m3=(rows8-15,kc1)
    const uint32_t a_base = sAb + (uint32_t)(warp_m * 64 + ((mm & 1) << 3) + r8) * 128;
    const uint32_t a_kc   = (uint32_t)(mm >> 1);
    // B x4: m0=(nf0,kc0) m1=(nf0,kc1) m2=(nf1,kc0) m3=(nf1,kc1)
    const uint32_t b_base = sBb + (uint32_t)(warp_n * 32 + ((mm >> 1) << 3) + r8) * 128;
    const uint32_t b_kc   = (uint32_t)(mm & 1);

    float acc[4][4][4];
#pragma unroll
    for (int mi = 0; mi < 4; mi++)
#pragma unroll
        for (int ni = 0; ni < 4; ni++)
#pragma unroll
            for (int f = 0; f < 4; f++) acc[mi][ni][f] = 0.f;

    for (int ch = 0; ch < 8; ++ch) {
        const int k0 = ch << 6;
        __syncthreads();

        // ---- stage A,B 128x64-half tiles, SW128 swizzle ----
#pragma unroll
        for (int s = 0; s < 4; ++s) {
            const int slot = tid + s * 256;         // 0..1023
            const int row  = slot >> 3;
            const int c    = slot & 7;              // 16B chunk (8 halves)
            const uint32_t dst = (uint32_t)(row * 128 + (((uint32_t)c << 4) ^ ((row & 7) << 4)));
            // A
            if (AHALF) {
                const __half* Ah = (const __half*)Av;
                *(uint4*)((char*)sA + dst) =
                    *(const uint4*)(Ah + (size_t)(m0 + row) * DMODEL + k0 + c * 8);
            } else {
                const float* Af = (const float*)Av;
                const float* ap = Af + (size_t)(m0 + row) * DMODEL + k0 + c * 8;
                float4 x = *(const float4*)ap;
                float4 y = *(const float4*)(ap + 4);
                uint4 u;
                u.x = h2u(__floats2half2_rn(x.x, x.y));
                u.y = h2u(__floats2half2_rn(x.z, x.w));
                u.z = h2u(__floats2half2_rn(y.x, y.y));
                u.w = h2u(__floats2half2_rn(y.z, y.w));
                *(uint4*)((char*)sA + dst) = u;
            }
            // W (always fp32 in gmem)
            {
                const float* wp = W + (size_t)(n0 + row) * DMODEL + k0 + c * 8;
                float4 x = *(const float4*)wp;
                float4 y = *(const float4*)(wp + 4);
                uint4 u;
                u.x = h2u(__floats2half2_rn(x.x, x.y));
                u.y = h2u(__floats2half2_rn(x.z, x.w));
                u.z = h2u(__floats2half2_rn(y.x, y.y));
                u.w = h2u(__floats2half2_rn(y.z, y.w));
                *(uint4*)((char*)sB + dst) = u;
            }
        }
        __syncthreads();

        // ---- 4 k16 steps per chunk ----
#pragma unroll
        for (int ks = 0; ks < 4; ks++) {
            uint32_t af[4][4];
#pragma unroll
            for (int mi = 0; mi < 4; mi++)
                ldsm_x4(af[mi], a_base + ((uint32_t)mi << 11)
                                + (((((uint32_t)ks << 1) | a_kc) << 4) ^ xr));
            uint32_t bf[2][4];
#pragma unroll
            for (int nfp = 0; nfp < 2; nfp++)
                ldsm_x4(bf[nfp], b_base + ((uint32_t)nfp << 11)
                                 + (((((uint32_t)ks << 1) | b_kc) << 4) ^ xr));
#pragma unroll
            for (int mi = 0; mi < 4; mi++)
#pragma unroll
                for (int nfp = 0; nfp < 2; nfp++) {
                    mma_f16_16x8x16(acc[mi][2 * nfp    ], af[mi], bf[nfp]    );
                    mma_f16_16x8x16(acc[mi][2 * nfp + 1], af[mi], bf[nfp] + 2);
                }
        }
    }

    // ---- epilogue ----
#pragma unroll
    for (int mi = 0; mi < 4; mi++) {
#pragma unroll
        for (int ni = 0; ni < 4; ni++) {
            const int row = m0 + warp_m * 64 + mi * 16 + g;
            const int col = n0 + warp_n * 32 + ni * 8 + t * 2;
            if (HOUT) {
                __half* Ch = (__half*)Cv;
                const int b = row >> 11, s = row & 2047;
                const int hh = col >> 6, dh = col & 63;
                size_t o0 = ((((size_t)b * NH + hh) * SEQQ + s) << 6) + dh;
                *(__half2*)(Ch + o0) =
                    __floats2half2_rn(acc[mi][ni][0] * scale, acc[mi][ni][1] * scale);
                *(__half2*)(Ch + o0 + ((size_t)8 << 6)) =
                    __floats2half2_rn(acc[mi][ni][2] * scale, acc[mi][ni][3] * scale);
            } else {
                float* Cf = (float*)Cv;
                size_t o0 = (size_t)row * DMODEL + col;
                *(float2*)(Cf + o0) = make_float2(acc[mi][ni][0], acc[mi][ni][1]);
                *(float2*)(Cf + o0 + (size_t)8 * DMODEL) =
                    make_float2(acc[mi][ni][2], acc[mi][ni][3]);
            }
        }
    }
}

// =====================================================================
// Flash attention, fp16 mma + ldmatrix (R9 passing version; ctx now fp16).
// =====================================================================
__global__ __launch_bounds__(256, 2)
void flash_attn(const int* __restrict__ valid_lens, __half* __restrict__ ctx)
{
    __shared__ __align__(16) __half sK[64 * 64];   // 8 KB, swizzled
    __shared__ __align__(16) __half sV[64 * 64];   // 8 KB, swizzled

    const int tid  = threadIdx.x;
    const int wr   = tid >> 5;
    const int lane = tid & 31;
    const int g    = lane >> 2;
    const int t    = lane & 3;

    const int bh = blockIdx.y;
    const int b  = bh >> 3;
    const int h  = bh & 7;
    const int q0 = blockIdx.x << 7;     // BQ = 128
    const int valid = valid_lens[b];

    const __half* Qw = g_qph + ((size_t)bh * SEQQ + q0 + wr * 16) * DHEAD;
    const __half* Kb = g_kph + (size_t)bh * SEQK * DHEAD;
    const __half* Vb = g_vph + (size_t)bh * SEQK * DHEAD;

    uint32_t qf[4][4];
#pragma unroll
    for (int j = 0; j < 4; j++) {
        qf[j][0] = *(const uint32_t*)(Qw + (g    ) * 64 + j * 16 + 2 * t);
        qf[j][1] = *(const uint32_t*)(Qw + (g + 8) * 64 + j * 16 + 2 * t);
        qf[j][2] = *(const uint32_t*)(Qw + (g    ) * 64 + j * 16 + 8 + 2 * t);
        qf[j][3] = *(const uint32_t*)(Qw + (g + 8) * 64 + j * 16 + 8 + 2 * t);
    }

    const uint32_t skb = smem_u32(sK);
    const uint32_t svb = smem_u32(sV);
    const int m  = lane >> 3;
    const int r8 = lane & 7;
    const uint32_t xr = (uint32_t)r8 << 4;
    const uint32_t k_rowbase = skb + (uint32_t)(((m >> 1) << 3) + r8) * 128;
    const uint32_t k_cbit    = (uint32_t)(m & 1) << 4;
    const uint32_t v_rowbase = svb + (uint32_t)(((m & 1) << 3) + r8) * 128;
    const uint32_t v_cbit    = (uint32_t)(m >> 1) << 4;

    float m0 = -1e30f, m1 = -1e30f;
    float l0 = 0.f,    l1 = 0.f;
    float o[8][4];
#pragma unroll
    for (int nf = 0; nf < 8; nf++)
#pragma unroll
        for (int f = 0; f < 4; f++) o[nf][f] = 0.f;

    const int nTiles = (valid + 63) >> 6;
    for (int tt = 0; tt < nTiles; tt++) {
        const int kbase = tt << 6;
        __syncthreads();

#pragma unroll
        for (int s = 0; s < 2; s++) {
            const int slot = tid + s * 256;
            const int k  = slot >> 3;
            const int c  = slot & 7;
            const uint32_t dst = (uint32_t)(k * 128 + (((uint32_t)c << 4) ^ ((k & 7) << 4)));
            *(uint4*)((char*)sK + dst) = *(const uint4*)(Kb + (size_t)(kbase + k) * 64 + c * 8);
            *(uint4*)((char*)sV + dst) = *(const uint4*)(Vb + (size_t)(kbase + k) * 64 + c * 8);
        }
        __syncthreads();

        float sc[8][4];
#pragma unroll
        for (int nf = 0; nf < 8; nf++)
#pragma unroll
            for (int f = 0; f < 4; f++) sc[nf][f] = 0.f;

#pragma unroll
        for (int ks = 0; ks < 4; ks++) {
            const uint32_t koff = (((uint32_t)ks << 5) | k_cbit) ^ xr;
#pragma unroll
            for (int nfp = 0; nfp < 4; nfp++) {
                uint32_t r[4];
                ldsm_x4(r, k_rowbase + ((uint32_t)nfp << 11) + koff);
                mma_f16_16x8x16(sc[2 * nfp    ], qf[ks], r    );
                mma_f16_16x8x16(sc[2 * nfp + 1], qf[ks], r + 2);
            }
        }

        if (kbase + 64 > valid) {
#pragma unroll
            for (int nf = 0; nf < 8; nf++) {
                const int c0 = kbase + nf * 8 + 2 * t;
                if (c0     >= valid) { sc[nf][0] = -1e30f; sc[nf][2] = -1e30f; }
                if (c0 + 1 >= valid) { sc[nf][1] = -1e30f; sc[nf][3] = -1e30f; }
            }
        }

        float mx0 = -1e30f, mx1 = -1e30f;
#pragma unroll
        for (int nf = 0; nf < 8; nf++) {
            mx0 = fmaxf(mx0, fmaxf(sc[nf][0], sc[nf][1]));
            mx1 = fmaxf(mx1, fmaxf(sc[nf][2], sc[nf][3]));
        }
        mx0 = fmaxf(mx0, __shfl_xor_sync(0xffffffffu, mx0, 1));
        mx0 = fmaxf(mx0, __shfl_xor_sync(0xffffffffu, mx0, 2));
        mx1 = fmaxf(mx1, __shfl_xor_sync(0xffffffffu, mx1, 1));
        mx1 = fmaxf(mx1, __shfl_xor_sync(0xffffffffu, mx1, 2));

        const float m0n = fmaxf(m0, mx0);
        const float m1n = fmaxf(m1, mx1);
        const float s0  = __expf(m0 - m0n);
        const float s1  = __expf(m1 - m1n);
        m0 = m0n; m1 = m1n;

        uint32_t pf[8][2];
        float l0a = 0.f, l1a = 0.f;
#pragma unroll
        for (int nf = 0; nf < 8; nf++) {
            const float p0 = __expf(sc[nf][0] - m0n);
            const float p1 = __expf(sc[nf][1] - m0n);
            const float p2 = __expf(sc[nf][2] - m1n);
            const float p3 = __expf(sc[nf][3] - m1n);
            l0a += p0 + p1;  l1a += p2 + p3;
            pf[nf][0] = h2u(__floats2half2_rn(p0, p1));
            pf[nf][1] = h2u(__floats2half2_rn(p2, p3));
        }
        l0 = l0 * s0 + l0a;
        l1 = l1 * s1 + l1a;
#pragma unroll
        for (int nf = 0; nf < 8; nf++) {
            o[nf][0] *= s0; o[nf][1] *= s0;
            o[nf][2] *= s1; o[nf][3] *= s1;
        }

#pragma unroll
        for (int ks = 0; ks < 4; ks++) {
            uint32_t af[4];
            af[0] = pf[2 * ks][0];
            af[1] = pf[2 * ks][1];
            af[2] = pf[2 * ks + 1][0];
            af[3] = pf[2 * ks + 1][1];
            const uint32_t vrow = v_rowbase + ((uint32_t)ks << 11);
#pragma unroll
            for (int nfp = 0; nfp < 4; nfp++) {
                uint32_t r[4];
                ldsm_x4_trans(r, vrow + ((((uint32_t)nfp << 5) + v_cbit) ^ xr));
                mma_f16_16x8x16(o[2 * nfp    ], af, r    );
                mma_f16_16x8x16(o[2 * nfp + 1], af, r + 2);
            }
        }
    }

    l0 += __shfl_xor_sync(0xffffffffu, l0, 1);
    l0 += __shfl_xor_sync(0xffffffffu, l0, 2);
    l1 += __shfl_xor_sync(0xffffffffu, l1, 1);
    l1 += __shfl_xor_sync(0xffffffffu, l1, 2);
    const float i0 = 1.f / l0;
    const float i1 = 1.f / l1;

    const int row0 = q0 + wr * 16 + g;
    __half* out0 = ctx + ((size_t)b * SEQQ + row0) * DMODEL + h * DHEAD;
    __half* out1 = out0 + (size_t)8 * DMODEL;
#pragma unroll
    for (int nf = 0; nf < 8; nf++) {
        const int col = nf * 8 + 2 * t;
        *(__half2*)(out0 + col) = __floats2half2_rn(o[nf][0] * i0, o[nf][1] * i0);
        *(__half2*)(out1 + col) = __floats2half2_rn(o[nf][2] * i1, o[nf][3] * i1);
    }
}

// =====================================================================
// launch
// =====================================================================
extern "C" void kernel_launch(void* const* d_in, const int* in_sizes, int n_in,
                              void* d_out, int out_size)
{
    const float* queries    = (const float*)d_in[0];
    const float* keys       = (const float*)d_in[1];
    const float* values     = (const float*)d_in[2];
    const int*   valid_lens = (const int*)  d_in[3];
    const float* W_q        = (const float*)d_in[4];
    const float* W_k        = (const float*)d_in[5];
    const float* W_v        = (const float*)d_in[6];
    const float* W_o        = (const float*)d_in[7];

    void *qp, *kp, *vp, *ctx;
    cudaGetSymbolAddress(&qp,  g_qph);
    cudaGetSymbolAddress(&kp,  g_kph);
    cudaGetSymbolAddress(&vp,  g_vph);
    cudaGetSymbolAddress(&ctx, g_ctxh);

    dim3 gridG(DMODEL / 128, (BATCH * SEQQ) / 128);   // (4, 64)
    gemm_f16<0,1><<<gridG, 256>>>(queries, W_q, qp, 0.125f);  // Q prescaled 1/sqrt(64)
    gemm_f16<0,1><<<gridG, 256>>>(keys,    W_k, kp, 1.f);
    gemm_f16<0,1><<<gridG, 256>>>(values,  W_v, vp, 1.f);

    dim3 gridF(SEQQ / 128, NBH);                      // (16, 32)
    flash_attn<<<gridF, 256>>>(valid_lens, (__half*)ctx);

    gemm_f16<1,0><<<gridG, 256>>>(ctx, W_o, d_out, 1.f);
}

// round 13
// speedup vs baseline: 8.5825x; 1.1404x over previous
#include <cuda_runtime.h>
#include <cuda_fp16.h>
#include <cstdint>

#define BATCH  4
#define SEQQ   2048
#define SEQK   2048
#define DMODEL 512
#define NH     8
#define DHEAD  64
#define NBH    (BATCH*NH)

// Q prescale: 1/sqrt(64) * log2(e)  (softmax runs in exp2 domain)
#define QSCALE 0.18033688011112042f

// ---------------- scratch (static device globals; no allocation) ----------------
__device__ __align__(16) __half g_qph[ (size_t)NBH*SEQQ*DHEAD ];  // [B,H,S,DH] fp16, prescaled
__device__ __align__(16) __half g_kph[ (size_t)NBH*SEQK*DHEAD ];  // fp16
__device__ __align__(16) __half g_vph[ (size_t)NBH*SEQK*DHEAD ];  // fp16
__device__ __align__(16) __half g_ctxh[ (size_t)BATCH*SEQQ*DMODEL ]; // [B,Q,D] fp16

// =====================================================================
// helpers (sm_80+ path; compiles on compute_103)
// =====================================================================
__device__ __forceinline__ void mma_f16_16x8x16(float* d, const uint32_t* a,
                                                const uint32_t* b) {
    asm volatile(
        "mma.sync.aligned.m16n8k16.row.col.f32.f16.f16.f32 "
        "{%0,%1,%2,%3}, {%4,%5,%6,%7}, {%8,%9}, {%0,%1,%2,%3};"
        : "+f"(d[0]), "+f"(d[1]), "+f"(d[2]), "+f"(d[3])
        : "r"(a[0]), "r"(a[1]), "r"(a[2]), "r"(a[3]), "r"(b[0]), "r"(b[1]));
}

__device__ __forceinline__ void ldsm_x4(uint32_t* r, uint32_t addr) {
    asm volatile("ldmatrix.sync.aligned.m8n8.x4.shared.b16 {%0,%1,%2,%3}, [%4];"
                 : "=r"(r[0]), "=r"(r[1]), "=r"(r[2]), "=r"(r[3]) : "r"(addr));
}
__device__ __forceinline__ void ldsm_x4_trans(uint32_t* r, uint32_t addr) {
    asm volatile("ldmatrix.sync.aligned.m8n8.x4.trans.shared.b16 {%0,%1,%2,%3}, [%4];"
                 : "=r"(r[0]), "=r"(r[1]), "=r"(r[2]), "=r"(r[3]) : "r"(addr));
}

__device__ __forceinline__ uint32_t smem_u32(const void* p) {
    uint32_t a;
    asm("{ .reg .u64 t; cvta.to.shared.u64 t, %1; cvt.u32.u64 %0, t; }" : "=r"(a) : "l"(p));
    return a;
}

__device__ __forceinline__ uint32_t h2u(__half2 h) {
    return *reinterpret_cast<uint32_t*>(&h);
}

__device__ __forceinline__ float ex2(float x) {
    float y;
    asm("ex2.approx.ftz.f32 %0, %1;" : "=f"(y) : "f"(x));
    return y;
}

__device__ __forceinline__ void cp16(uint32_t dst, const void* src) {
    asm volatile("cp.async.cg.shared.global [%0], [%1], 16;" :: "r"(dst), "l"(src));
}
#define CP_COMMIT() asm volatile("cp.async.commit_group;" ::: "memory")
#define CP_WAIT0()  asm volatile("cp.async.wait_group 0;"  ::: "memory")

// =====================================================================
// fp16 HMMA GEMM body: C[M,512] = A[M,512] @ W[512,512]^T
// 128x128 block tile, 8 warps (2x4), warp tile 64x32, BK=64.
// SW128-swizzled fp16 smem + ldmatrix. AHALF: A fp16 vs fp32 gmem.
// HOUT=1: scaled fp16 scatter to [B,H,S,DH]; HOUT=0: fp32 [M,N].
// =====================================================================
template<int AHALF, int HOUT>
__device__ __forceinline__ void gemm_body(const void* __restrict__ Av,
                                          const float* __restrict__ W,
                                          void* __restrict__ Cv, float scale)
{
    __shared__ __align__(16) __half sA[128 * 64];   // 16 KB
    __shared__ __align__(16) __half sB[128 * 64];   // 16 KB

    const int tid  = threadIdx.x;
    const int wid  = tid >> 5;
    const int lane = tid & 31;
    const int m0   = blockIdx.y * 128;
    const int n0   = blockIdx.x * 128;

    const int warp_m = wid >> 2;
    const int warp_n = wid & 3;
    const int g  = lane >> 2;
    const int t  = lane & 3;
    const int mm = lane >> 3;
    const int r8 = lane & 7;

    const uint32_t sAb = smem_u32(sA);
    const uint32_t sBb = smem_u32(sB);
    const uint32_t xr  = (uint32_t)r8 << 4;
    const uint32_t a_base = sAb + (uint32_t)(warp_m * 64 + ((mm & 1) << 3) + r8) * 128;
    const uint32_t a_kc   = (uint32_t)(mm >> 1);
    const uint32_t b_base = sBb + (uint32_t)(warp_n * 32 + ((mm >> 1) << 3) + r8) * 128;
    const uint32_t b_kc   = (uint32_t)(mm & 1);

    float acc[4][4][4];
#pragma unroll
    for (int mi = 0; mi < 4; mi++)
#pragma unroll
        for (int ni = 0; ni < 4; ni++)
#pragma unroll
            for (int f = 0; f < 4; f++) acc[mi][ni][f] = 0.f;

    for (int ch = 0; ch < 8; ++ch) {
        const int k0 = ch << 6;
        __syncthreads();

#pragma unroll
        for (int s = 0; s < 4; ++s) {
            const int slot = tid + s * 256;
            const int row  = slot >> 3;
            const int c    = slot & 7;
            const uint32_t dst = (uint32_t)(row * 128 + (((uint32_t)c << 4) ^ ((row & 7) << 4)));
            if (AHALF) {
                const __half* Ah = (const __half*)Av;
                *(uint4*)((char*)sA + dst) =
                    *(const uint4*)(Ah + (size_t)(m0 + row) * DMODEL + k0 + c * 8);
            } else {
                const float* Af = (const float*)Av;
                const float* ap = Af + (size_t)(m0 + row) * DMODEL + k0 + c * 8;
                float4 x = *(const float4*)ap;
                float4 y = *(const float4*)(ap + 4);
                uint4 u;
                u.x = h2u(__floats2half2_rn(x.x, x.y));
                u.y = h2u(__floats2half2_rn(x.z, x.w));
                u.z = h2u(__floats2half2_rn(y.x, y.y));
                u.w = h2u(__floats2half2_rn(y.z, y.w));
                *(uint4*)((char*)sA + dst) = u;
            }
            {
                const float* wp = W + (size_t)(n0 + row) * DMODEL + k0 + c * 8;
                float4 x = *(const float4*)wp;
                float4 y = *(const float4*)(wp + 4);
                uint4 u;
                u.x = h2u(__floats2half2_rn(x.x, x.y));
                u.y = h2u(__floats2half2_rn(x.z, x.w));
                u.z = h2u(__floats2half2_rn(y.x, y.y));
                u.w = h2u(__floats2half2_rn(y.z, y.w));
                *(uint4*)((char*)sB + dst) = u;
            }
        }
        __syncthreads();

#pragma unroll
        for (int ks = 0; ks < 4; ks++) {
            uint32_t af[4][4];
#pragma unroll
            for (int mi = 0; mi < 4; mi++)
                ldsm_x4(af[mi], a_base + ((uint32_t)mi << 11)
                                + (((((uint32_t)ks << 1) | a_kc) << 4) ^ xr));
            uint32_t bf[2][4];
#pragma unroll
            for (int nfp = 0; nfp < 2; nfp++)
                ldsm_x4(bf[nfp], b_base + ((uint32_t)nfp << 11)
                                 + (((((uint32_t)ks << 1) | b_kc) << 4) ^ xr));
#pragma unroll
            for (int mi = 0; mi < 4; mi++)
#pragma unroll
                for (int nfp = 0; nfp < 2; nfp++) {
                    mma_f16_16x8x16(acc[mi][2 * nfp    ], af[mi], bf[nfp]    );
                    mma_f16_16x8x16(acc[mi][2 * nfp + 1], af[mi], bf[nfp] + 2);
                }
        }
    }

#pragma unroll
    for (int mi = 0; mi < 4; mi++) {
#pragma unroll
        for (int ni = 0; ni < 4; ni++) {
            const int row = m0 + warp_m * 64 + mi * 16 + g;
            const int col = n0 + warp_n * 32 + ni * 8 + t * 2;
            if (HOUT) {
                __half* Ch = (__half*)Cv;
                const int b = row >> 11, s = row & 2047;
                const int hh = col >> 6, dh = col & 63;
                size_t o0 = ((((size_t)b * NH + hh) * SEQQ + s) << 6) + dh;
                *(__half2*)(Ch + o0) =
                    __floats2half2_rn(acc[mi][ni][0] * scale, acc[mi][ni][1] * scale);
                *(__half2*)(Ch + o0 + ((size_t)8 << 6)) =
                    __floats2half2_rn(acc[mi][ni][2] * scale, acc[mi][ni][3] * scale);
            } else {
                float* Cf = (float*)Cv;
                size_t o0 = (size_t)row * DMODEL + col;
                *(float2*)(Cf + o0) = make_float2(acc[mi][ni][0], acc[mi][ni][1]);
                *(float2*)(Cf + o0 + (size_t)8 * DMODEL) =
                    make_float2(acc[mi][ni][2], acc[mi][ni][3]);
            }
        }
    }
}

// Fused Q/K/V projections: gridDim.z selects the GEMM (better wave fill).
__global__ __launch_bounds__(256, 2)
void gemm_qkv(const float* __restrict__ Aq, const float* __restrict__ Ak,
              const float* __restrict__ Avv,
              const float* __restrict__ Wq, const float* __restrict__ Wk,
              const float* __restrict__ Wv,
              __half* __restrict__ Cq, __half* __restrict__ Ck,
              __half* __restrict__ Cv)
{
    const float* A; const float* W; __half* C; float scale;
    if (blockIdx.z == 0)      { A = Aq;  W = Wq; C = Cq; scale = QSCALE; }
    else if (blockIdx.z == 1) { A = Ak;  W = Wk; C = Ck; scale = 1.f; }
    else                      { A = Avv; W = Wv; C = Cv; scale = 1.f; }
    gemm_body<0, 1>(A, W, C, scale);
}

__global__ __launch_bounds__(256, 2)
void gemm_out(const __half* __restrict__ ctx, const float* __restrict__ Wo,
              float* __restrict__ out)
{
    gemm_body<1, 0>(ctx, Wo, out, 1.f);
}

// =====================================================================
// Flash attention: fp16 mma + ldmatrix + cp.async double-buffered K/V.
// Block: 128 queries x one (b,h), 8 warps x 16 rows, BK=64 tiles.
// Softmax in exp2 domain (log2e folded into Q prescale).
// =====================================================================
__global__ __launch_bounds__(256, 2)
void flash_attn(const int* __restrict__ valid_lens, __half* __restrict__ ctx)
{
    __shared__ __align__(16) __half sK[2][64 * 64];   // 2 x 8 KB
    __shared__ __align__(16) __half sV[2][64 * 64];   // 2 x 8 KB

    const int tid  = threadIdx.x;
    const int wr   = tid >> 5;
    const int lane = tid & 31;
    const int g    = lane >> 2;
    const int t    = lane & 3;

    const int bh = blockIdx.y;
    const int b  = bh >> 3;
    const int h  = bh & 7;
    const int q0 = blockIdx.x << 7;     // BQ = 128
    const int valid = valid_lens[b];

    const __half* Qw = g_qph + ((size_t)bh * SEQQ + q0 + wr * 16) * DHEAD;
    const __half* Kb = g_kph + (size_t)bh * SEQK * DHEAD;
    const __half* Vb = g_vph + (size_t)bh * SEQK * DHEAD;

    // ---- Q A-frags direct from gmem ----
    uint32_t qf[4][4];
#pragma unroll
    for (int j = 0; j < 4; j++) {
        qf[j][0] = *(const uint32_t*)(Qw + (g    ) * 64 + j * 16 + 2 * t);
        qf[j][1] = *(const uint32_t*)(Qw + (g + 8) * 64 + j * 16 + 2 * t);
        qf[j][2] = *(const uint32_t*)(Qw + (g    ) * 64 + j * 16 + 8 + 2 * t);
        qf[j][3] = *(const uint32_t*)(Qw + (g + 8) * 64 + j * 16 + 8 + 2 * t);
    }

    // ---- staging slots (2 x 16B chunks per thread per operand) ----
    const int k0s = tid >> 3,        c0s = tid & 7;
    const int k1s = (tid + 256) >> 3, c1s = (tid + 256) & 7;
    const uint32_t off0 = (uint32_t)(k0s * 128 + (((uint32_t)c0s << 4) ^ ((k0s & 7) << 4)));
    const uint32_t off1 = (uint32_t)(k1s * 128 + (((uint32_t)c1s << 4) ^ ((k1s & 7) << 4)));
    const size_t gm0 = (size_t)k0s * 64 + c0s * 8;
    const size_t gm1 = (size_t)k1s * 64 + c1s * 8;

    const uint32_t skb = smem_u32(sK);
    const uint32_t svb = smem_u32(sV);
    const int m  = lane >> 3;
    const int r8 = lane & 7;
    const uint32_t xr = (uint32_t)r8 << 4;
    const uint32_t k_rowbase = skb + (uint32_t)(((m >> 1) << 3) + r8) * 128;
    const uint32_t k_cbit    = (uint32_t)(m & 1) << 4;
    const uint32_t v_rowbase = svb + (uint32_t)(((m & 1) << 3) + r8) * 128;
    const uint32_t v_cbit    = (uint32_t)(m >> 1) << 4;

    float m0 = -1e30f, m1 = -1e30f;
    float l0 = 0.f,    l1 = 0.f;
    float o[8][4];
#pragma unroll
    for (int nf = 0; nf < 8; nf++)
#pragma unroll
        for (int f = 0; f < 4; f++) o[nf][f] = 0.f;

    const int nTiles = (valid + 63) >> 6;

    // ---- prologue: stage tile 0 into buf 0 ----
    {
        const __half* Kt = Kb;  const __half* Vt = Vb;
        cp16(skb + off0, Kt + gm0); cp16(skb + off1, Kt + gm1);
        cp16(svb + off0, Vt + gm0); cp16(svb + off1, Vt + gm1);
        CP_COMMIT();
    }

    for (int tt = 0; tt < nTiles; tt++) {
        const int buf = tt & 1;
        const uint32_t bofs = (uint32_t)buf << 13;   // 8192 B

        CP_WAIT0();          // tile tt data arrived
        __syncthreads();     // visible to all; all warps done with buf^1

        // ---- stage tile tt+1 into the other buffer ----
        if (tt + 1 < nTiles) {
            const uint32_t ob = (uint32_t)(buf ^ 1) << 13;
            const __half* Kt = Kb + (size_t)(tt + 1) * 64 * 64;
            const __half* Vt = Vb + (size_t)(tt + 1) * 64 * 64;
            cp16(skb + ob + off0, Kt + gm0); cp16(skb + ob + off1, Kt + gm1);
            cp16(svb + ob + off0, Vt + gm0); cp16(svb + ob + off1, Vt + gm1);
            CP_COMMIT();
        }

        const int kbase = tt << 6;

        // ---- S = Q K^T (log2-scaled) ----
        float sc[8][4];
#pragma unroll
        for (int nf = 0; nf < 8; nf++)
#pragma unroll
            for (int f = 0; f < 4; f++) sc[nf][f] = 0.f;

#pragma unroll
        for (int ks = 0; ks < 4; ks++) {
            const uint32_t koff = (((uint32_t)ks << 5) | k_cbit) ^ xr;
#pragma unroll
            for (int nfp = 0; nfp < 4; nfp++) {
                uint32_t r[4];
                ldsm_x4(r, k_rowbase + bofs + ((uint32_t)nfp << 11) + koff);
                mma_f16_16x8x16(sc[2 * nfp    ], qf[ks], r    );
                mma_f16_16x8x16(sc[2 * nfp + 1], qf[ks], r + 2);
            }
        }

        // ---- mask tail columns ----
        if (kbase + 64 > valid) {
#pragma unroll
            for (int nf = 0; nf < 8; nf++) {
                const int c0 = kbase + nf * 8 + 2 * t;
                if (c0     >= valid) { sc[nf][0] = -1e30f; sc[nf][2] = -1e30f; }
                if (c0 + 1 >= valid) { sc[nf][1] = -1e30f; sc[nf][3] = -1e30f; }
            }
        }

        // ---- online softmax (exp2 domain) ----
        float mx0 = -1e30f, mx1 = -1e30f;
#pragma unroll
        for (int nf = 0; nf < 8; nf++) {
            mx0 = fmaxf(mx0, fmaxf(sc[nf][0], sc[nf][1]));
            mx1 = fmaxf(mx1, fmaxf(sc[nf][2], sc[nf][3]));
        }
        mx0 = fmaxf(mx0, __shfl_xor_sync(0xffffffffu, mx0, 1));
        mx0 = fmaxf(mx0, __shfl_xor_sync(0xffffffffu, mx0, 2));
        mx1 = fmaxf(mx1, __shfl_xor_sync(0xffffffffu, mx1, 1));
        mx1 = fmaxf(mx1, __shfl_xor_sync(0xffffffffu, mx1, 2));

        const float m0n = fmaxf(m0, mx0);
        const float m1n = fmaxf(m1, mx1);
        const float s0  = ex2(m0 - m0n);
        const float s1  = ex2(m1 - m1n);
        m0 = m0n; m1 = m1n;

        uint32_t pf[8][2];
        float l0a = 0.f, l1a = 0.f;
#pragma unroll
        for (int nf = 0; nf < 8; nf++) {
            const float p0 = ex2(sc[nf][0] - m0n);
            const float p1 = ex2(sc[nf][1] - m0n);
            const float p2 = ex2(sc[nf][2] - m1n);
            const float p3 = ex2(sc[nf][3] - m1n);
            l0a += p0 + p1;  l1a += p2 + p3;
            pf[nf][0] = h2u(__floats2half2_rn(p0, p1));
            pf[nf][1] = h2u(__floats2half2_rn(p2, p3));
        }
        l0 = l0 * s0 + l0a;
        l1 = l1 * s1 + l1a;
#pragma unroll
        for (int nf = 0; nf < 8; nf++) {
            o[nf][0] *= s0; o[nf][1] *= s0;
            o[nf][2] *= s1; o[nf][3] *= s1;
        }

        // ---- O += P V ----
#pragma unroll
        for (int ks = 0; ks < 4; ks++) {
            uint32_t af[4];
            af[0] = pf[2 * ks][0];
            af[1] = pf[2 * ks][1];
            af[2] = pf[2 * ks + 1][0];
            af[3] = pf[2 * ks + 1][1];
            const uint32_t vrow = v_rowbase + bofs + ((uint32_t)ks << 11);
#pragma unroll
            for (int nfp = 0; nfp < 4; nfp++) {
                uint32_t r[4];
                ldsm_x4_trans(r, vrow + ((((uint32_t)nfp << 5) + v_cbit) ^ xr));
                mma_f16_16x8x16(o[2 * nfp    ], af, r    );
                mma_f16_16x8x16(o[2 * nfp + 1], af, r + 2);
            }
        }
    }

    // ---- epilogue ----
    l0 += __shfl_xor_sync(0xffffffffu, l0, 1);
    l0 += __shfl_xor_sync(0xffffffffu, l0, 2);
    l1 += __shfl_xor_sync(0xffffffffu, l1, 1);
    l1 += __shfl_xor_sync(0xffffffffu, l1, 2);
    const float i0 = 1.f / l0;
    const float i1 = 1.f / l1;

    const int row0 = q0 + wr * 16 + g;
    __half* out0 = ctx + ((size_t)b * SEQQ + row0) * DMODEL + h * DHEAD;
    __half* out1 = out0 + (size_t)8 * DMODEL;
#pragma unroll
    for (int nf = 0; nf < 8; nf++) {
        const int col = nf * 8 + 2 * t;
        *(__half2*)(out0 + col) = __floats2half2_rn(o[nf][0] * i0, o[nf][1] * i0);
        *(__half2*)(out1 + col) = __floats2half2_rn(o[nf][2] * i1, o[nf][3] * i1);
    }
}

// =====================================================================
// launch
// =====================================================================
extern "C" void kernel_launch(void* const* d_in, const int* in_sizes, int n_in,
                              void* d_out, int out_size)
{
    const float* queries    = (const float*)d_in[0];
    const float* keys       = (const float*)d_in[1];
    const float* values     = (const float*)d_in[2];
    const int*   valid_lens = (const int*)  d_in[3];
    const float* W_q        = (const float*)d_in[4];
    const float* W_k        = (const float*)d_in[5];
    const float* W_v        = (const float*)d_in[6];
    const float* W_o        = (const float*)d_in[7];

    void *qp, *kp, *vp, *ctx;
    cudaGetSymbolAddress(&qp,  g_qph);
    cudaGetSymbolAddress(&kp,  g_kph);
    cudaGetSymbolAddress(&vp,  g_vph);
    cudaGetSymbolAddress(&ctx, g_ctxh);

    dim3 gridQKV(DMODEL / 128, (BATCH * SEQQ) / 128, 3);   // (4, 64, 3)
    gemm_qkv<<<gridQKV, 256>>>(queries, keys, values, W_q, W_k, W_v,
                               (__half*)qp, (__half*)kp, (__half*)vp);

    dim3 gridF(SEQQ / 128, NBH);                           // (16, 32)
    flash_attn<<<gridF, 256>>>(valid_lens, (__half*)ctx);

    dim3 gridO(DMODEL / 128, (BATCH * SEQQ) / 128);        // (4, 64)
    gemm_out<<<gridO, 256>>>((const __half*)ctx, W_o, (float*)d_out);
}

// round 14
// speedup vs baseline: 10.4404x; 1.2165x over previous
#include <cuda_runtime.h>
#include <cuda_fp16.h>
#include <cstdint>

#define BATCH  4
#define SEQQ   2048
#define SEQK   2048
#define DMODEL 512
#define NH     8
#define DHEAD  64
#define NBH    (BATCH*NH)

// Q prescale: 1/sqrt(64) * log2(e)  (softmax runs in exp2 domain)
#define QSCALE 0.18033688011112042f

// ---------------- scratch (static device globals; no allocation) ----------------
__device__ __align__(16) __half g_qph[ (size_t)NBH*SEQQ*DHEAD ];   // [B,H,S,DH] fp16 (prescaled)
__device__ __align__(16) __half g_kph[ (size_t)NBH*SEQK*DHEAD ];
__device__ __align__(16) __half g_vph[ (size_t)NBH*SEQK*DHEAD ];
__device__ __align__(16) __half g_ctxh[ (size_t)BATCH*SEQQ*DMODEL ]; // [B,Q,D] fp16
__device__ __align__(16) __half g_wh [ (size_t)4*DMODEL*DMODEL ];    // fp16 weights (Wq*QSCALE, Wk, Wv, Wo)
__device__ __align__(16) __half g_xh [ (size_t)3*BATCH*SEQQ*DMODEL ];// fp16 inputs (q,k,v)

// =====================================================================
// helpers (sm_80+ path; compiles on compute_103)
// =====================================================================
__device__ __forceinline__ void mma_f16_16x8x16(float* d, const uint32_t* a,
                                                const uint32_t* b) {
    asm volatile(
        "mma.sync.aligned.m16n8k16.row.col.f32.f16.f16.f32 "
        "{%0,%1,%2,%3}, {%4,%5,%6,%7}, {%8,%9}, {%0,%1,%2,%3};"
        : "+f"(d[0]), "+f"(d[1]), "+f"(d[2]), "+f"(d[3])
        : "r"(a[0]), "r"(a[1]), "r"(a[2]), "r"(a[3]), "r"(b[0]), "r"(b[1]));
}

__device__ __forceinline__ void ldsm_x4(uint32_t* r, uint32_t addr) {
    asm volatile("ldmatrix.sync.aligned.m8n8.x4.shared.b16 {%0,%1,%2,%3}, [%4];"
                 : "=r"(r[0]), "=r"(r[1]), "=r"(r[2]), "=r"(r[3]) : "r"(addr));
}
__device__ __forceinline__ void ldsm_x4_trans(uint32_t* r, uint32_t addr) {
    asm volatile("ldmatrix.sync.aligned.m8n8.x4.trans.shared.b16 {%0,%1,%2,%3}, [%4];"
                 : "=r"(r[0]), "=r"(r[1]), "=r"(r[2]), "=r"(r[3]) : "r"(addr));
}

__device__ __forceinline__ uint32_t smem_u32(const void* p) {
    uint32_t a;
    asm("{ .reg .u64 t; cvta.to.shared.u64 t, %1; cvt.u32.u64 %0, t; }" : "=r"(a) : "l"(p));
    return a;
}

__device__ __forceinline__ uint32_t h2u(__half2 h) {
    return *reinterpret_cast<uint32_t*>(&h);
}

__device__ __forceinline__ float ex2(float x) {
    float y;
    asm("ex2.approx.ftz.f32 %0, %1;" : "=f"(y) : "f"(x));
    return y;
}

__device__ __forceinline__ void cp16(uint32_t dst, const void* src) {
    asm volatile("cp.async.cg.shared.global [%0], [%1], 16;" :: "r"(dst), "l"(src));
}
#define CP_COMMIT() asm volatile("cp.async.commit_group;" ::: "memory")
#define CP_WAIT0()  asm volatile("cp.async.wait_group 0;"  ::: "memory")

// =====================================================================
// fp32 -> fp16 converters (one-shot pre-pass)
// =====================================================================
__global__ __launch_bounds__(256)
void cvt_w(const float* __restrict__ Wq, const float* __restrict__ Wk,
           const float* __restrict__ Wv, const float* __restrict__ Wo)
{
    const int z = blockIdx.y;
    const float* src = (z == 0) ? Wq : (z == 1) ? Wk : (z == 2) ? Wv : Wo;
    const float scale = (z == 0) ? QSCALE : 1.f;
    __half* dst = g_wh + (size_t)z * DMODEL * DMODEL;
    const size_t i = ((size_t)blockIdx.x * 256 + threadIdx.x) * 8;
    float4 x = *(const float4*)(src + i);
    float4 y = *(const float4*)(src + i + 4);
    uint4 u;
    u.x = h2u(__floats2half2_rn(x.x * scale, x.y * scale));
    u.y = h2u(__floats2half2_rn(x.z * scale, x.w * scale));
    u.z = h2u(__floats2half2_rn(y.x * scale, y.y * scale));
    u.w = h2u(__floats2half2_rn(y.z * scale, y.w * scale));
    *(uint4*)(dst + i) = u;
}

__global__ __launch_bounds__(256)
void cvt_x(const float* __restrict__ Xq, const float* __restrict__ Xk,
           const float* __restrict__ Xv)
{
    const int z = blockIdx.y;
    const float* src = (z == 0) ? Xq : (z == 1) ? Xk : Xv;
    __half* dst = g_xh + (size_t)z * BATCH * SEQQ * DMODEL;
    const size_t i = ((size_t)blockIdx.x * 256 + threadIdx.x) * 8;
    float4 x = *(const float4*)(src + i);
    float4 y = *(const float4*)(src + i + 4);
    uint4 u;
    u.x = h2u(__floats2half2_rn(x.x, x.y));
    u.y = h2u(__floats2half2_rn(x.z, x.w));
    u.z = h2u(__floats2half2_rn(y.x, y.y));
    u.w = h2u(__floats2half2_rn(y.z, y.w));
    *(uint4*)(dst + i) = u;
}

// =====================================================================
// all-fp16 HMMA GEMM: C[M,512] = A[M,512] @ W[N,512]^T
// 128x128 block tile, 8 warps (2x4), warp tile 64x32.
// BK=32 chunks, cp.async double-buffered (1 barrier per chunk).
// smem rows = 32 halves (64B), swizzle: chunk c -> c ^ ((row>>1)&3).
// (ldmatrix bank index = (4r + (c ^ ((r>>1)&3))) mod 8 -> all distinct.)
// HOUT=1: fp16 scatter to [B,H,S,DH]; HOUT=0: fp32 [M,N].
// =====================================================================
template<int HOUT>
__device__ __forceinline__ void gemm_h_body(const __half* __restrict__ A,
                                            const __half* __restrict__ W,
                                            void* __restrict__ Cv)
{
    __shared__ __align__(16) __half sA[2][128 * 32];   // 2 x 8 KB
    __shared__ __align__(16) __half sB[2][128 * 32];   // 2 x 8 KB

    const int tid  = threadIdx.x;
    const int wid  = tid >> 5;
    const int lane = tid & 31;
    const int m0   = blockIdx.y * 128;
    const int n0   = blockIdx.x * 128;

    const int warp_m = wid >> 2;        // 0..1 -> *64 rows
    const int warp_n = wid & 3;         // 0..3 -> *32 cols
    const int g  = lane >> 2;
    const int t  = lane & 3;
    const int mm = lane >> 3;           // ldmatrix matrix idx 0..3
    const int r8 = lane & 7;

    const uint32_t sAb = smem_u32(sA);
    const uint32_t sBb = smem_u32(sB);
    const uint32_t axor = (uint32_t)((r8 >> 1) & 3);
    // A frag rows: warp_m*64 + mi*16 + (mm&1)*8 + r8 ; row stride 64 B
    const uint32_t a_base = sAb + (uint32_t)(warp_m * 64 + ((mm & 1) << 3) + r8) * 64;
    // B frag rows: warp_n*32 + (mm>>1)*8 + r8
    const uint32_t b_base = sBb + (uint32_t)(warp_n * 32 + ((mm >> 1) << 3) + r8) * 64;

    // staging slots: 2 x 16B per thread per operand per chunk
    const int row0 = tid >> 2,           c0 = tid & 3;
    const int row1 = (tid + 256) >> 2,   c1 = (tid + 256) & 3;
    const uint32_t d0 = (uint32_t)(row0 * 64 + (((uint32_t)c0 ^ ((row0 >> 1) & 3)) << 4));
    const uint32_t d1 = (uint32_t)(row1 * 64 + (((uint32_t)c1 ^ ((row1 >> 1) & 3)) << 4));
    const __half* Ag0 = A + (size_t)(m0 + row0) * DMODEL + c0 * 8;
    const __half* Ag1 = A + (size_t)(m0 + row1) * DMODEL + c1 * 8;
    const __half* Wg0 = W + (size_t)(n0 + row0) * DMODEL + c0 * 8;
    const __half* Wg1 = W + (size_t)(n0 + row1) * DMODEL + c1 * 8;

    float acc[4][4][4];
#pragma unroll
    for (int mi = 0; mi < 4; mi++)
#pragma unroll
        for (int ni = 0; ni < 4; ni++)
#pragma unroll
            for (int f = 0; f < 4; f++) acc[mi][ni][f] = 0.f;

    // prologue: stage chunk 0 into buffer 0
    cp16(sAb + d0, Ag0); cp16(sAb + d1, Ag1);
    cp16(sBb + d0, Wg0); cp16(sBb + d1, Wg1);
    CP_COMMIT();

    for (int ch = 0; ch < 16; ++ch) {
        const uint32_t bofs = (uint32_t)(ch & 1) << 13;   // 8192 B

        CP_WAIT0();
        __syncthreads();

        if (ch + 1 < 16) {
            const uint32_t ob = (uint32_t)((ch + 1) & 1) << 13;
            const int k1 = (ch + 1) << 5;
            cp16(sAb + ob + d0, Ag0 + k1); cp16(sAb + ob + d1, Ag1 + k1);
            cp16(sBb + ob + d0, Wg0 + k1); cp16(sBb + ob + d1, Wg1 + k1);
            CP_COMMIT();
        }

#pragma unroll
        for (int ks = 0; ks < 2; ks++) {
            uint32_t af[4][4];
            const uint32_t ac = ((((uint32_t)(ks << 1) | (uint32_t)(mm >> 1)) ^ axor) << 4);
#pragma unroll
            for (int mi = 0; mi < 4; mi++)
                ldsm_x4(af[mi], a_base + bofs + ((uint32_t)mi << 10) + ac);
            uint32_t bf[2][4];
            const uint32_t bc = ((((uint32_t)(ks << 1) | (uint32_t)(mm & 1)) ^ axor) << 4);
#pragma unroll
            for (int nfp = 0; nfp < 2; nfp++)
                ldsm_x4(bf[nfp], b_base + bofs + ((uint32_t)nfp << 10) + bc);
#pragma unroll
            for (int mi = 0; mi < 4; mi++)
#pragma unroll
                for (int nfp = 0; nfp < 2; nfp++) {
                    mma_f16_16x8x16(acc[mi][2 * nfp    ], af[mi], bf[nfp]    );
                    mma_f16_16x8x16(acc[mi][2 * nfp + 1], af[mi], bf[nfp] + 2);
                }
        }
    }

#pragma unroll
    for (int mi = 0; mi < 4; mi++) {
#pragma unroll
        for (int ni = 0; ni < 4; ni++) {
            const int row = m0 + warp_m * 64 + mi * 16 + g;
            const int col = n0 + warp_n * 32 + ni * 8 + t * 2;
            if (HOUT) {
                __half* Ch = (__half*)Cv;
                const int b = row >> 11, s = row & 2047;
                const int hh = col >> 6, dh = col & 63;
                size_t o0 = ((((size_t)b * NH + hh) * SEQQ + s) << 6) + dh;
                *(__half2*)(Ch + o0) =
                    __floats2half2_rn(acc[mi][ni][0], acc[mi][ni][1]);
                *(__half2*)(Ch + o0 + ((size_t)8 << 6)) =
                    __floats2half2_rn(acc[mi][ni][2], acc[mi][ni][3]);
            } else {
                float* Cf = (float*)Cv;
                size_t o0 = (size_t)row * DMODEL + col;
                *(float2*)(Cf + o0) = make_float2(acc[mi][ni][0], acc[mi][ni][1]);
                *(float2*)(Cf + o0 + (size_t)8 * DMODEL) =
                    make_float2(acc[mi][ni][2], acc[mi][ni][3]);
            }
        }
    }
}

// Fused Q/K/V projections (blockIdx.z selects GEMM).
__global__ __launch_bounds__(256, 2)
void gemm_qkv(__half* __restrict__ Cq, __half* __restrict__ Ck,
              __half* __restrict__ Cv)
{
    const int z = blockIdx.z;
    const __half* A = g_xh + (size_t)z * BATCH * SEQQ * DMODEL;
    const __half* W = g_wh + (size_t)z * DMODEL * DMODEL;
    __half* C = (z == 0) ? Cq : (z == 1) ? Ck : Cv;
    gemm_h_body<1>(A, W, C);
}

__global__ __launch_bounds__(256, 2)
void gemm_out(const __half* __restrict__ ctx, float* __restrict__ out)
{
    gemm_h_body<0>(ctx, g_wh + (size_t)3 * DMODEL * DMODEL, out);
}

// =====================================================================
// Flash attention: fp16 mma + ldmatrix + cp.async double-buffered K/V.
// (unchanged from R13 passing version)
// =====================================================================
__global__ __launch_bounds__(256, 2)
void flash_attn(const int* __restrict__ valid_lens, __half* __restrict__ ctx)
{
    __shared__ __align__(16) __half sK[2][64 * 64];   // 2 x 8 KB
    __shared__ __align__(16) __half sV[2][64 * 64];   // 2 x 8 KB

    const int tid  = threadIdx.x;
    const int wr   = tid >> 5;
    const int lane = tid & 31;
    const int g    = lane >> 2;
    const int t    = lane & 3;

    const int bh = blockIdx.y;
    const int b  = bh >> 3;
    const int h  = bh & 7;
    const int q0 = blockIdx.x << 7;     // BQ = 128
    const int valid = valid_lens[b];

    const __half* Qw = g_qph + ((size_t)bh * SEQQ + q0 + wr * 16) * DHEAD;
    const __half* Kb = g_kph + (size_t)bh * SEQK * DHEAD;
    const __half* Vb = g_vph + (size_t)bh * SEQK * DHEAD;

    uint32_t qf[4][4];
#pragma unroll
    for (int j = 0; j < 4; j++) {
        qf[j][0] = *(const uint32_t*)(Qw + (g    ) * 64 + j * 16 + 2 * t);
        qf[j][1] = *(const uint32_t*)(Qw + (g + 8) * 64 + j * 16 + 2 * t);
        qf[j][2] = *(const uint32_t*)(Qw + (g    ) * 64 + j * 16 + 8 + 2 * t);
        qf[j][3] = *(const uint32_t*)(Qw + (g + 8) * 64 + j * 16 + 8 + 2 * t);
    }

    const int k0s = tid >> 3,         c0s = tid & 7;
    const int k1s = (tid + 256) >> 3, c1s = (tid + 256) & 7;
    const uint32_t off0 = (uint32_t)(k0s * 128 + (((uint32_t)c0s << 4) ^ ((k0s & 7) << 4)));
    const uint32_t off1 = (uint32_t)(k1s * 128 + (((uint32_t)c1s << 4) ^ ((k1s & 7) << 4)));
    const size_t gm0 = (size_t)k0s * 64 + c0s * 8;
    const size_t gm1 = (size_t)k1s * 64 + c1s * 8;

    const uint32_t skb = smem_u32(sK);
    const uint32_t svb = smem_u32(sV);
    const int m  = lane >> 3;
    const int r8 = lane & 7;
    const uint32_t xr = (uint32_t)r8 << 4;
    const uint32_t k_rowbase = skb + (uint32_t)(((m >> 1) << 3) + r8) * 128;
    const uint32_t k_cbit    = (uint32_t)(m & 1) << 4;
    const uint32_t v_rowbase = svb + (uint32_t)(((m & 1) << 3) + r8) * 128;
    const uint32_t v_cbit    = (uint32_t)(m >> 1) << 4;

    float m0 = -1e30f, m1 = -1e30f;
    float l0 = 0.f,    l1 = 0.f;
    float o[8][4];
#pragma unroll
    for (int nf = 0; nf < 8; nf++)
#pragma unroll
        for (int f = 0; f < 4; f++) o[nf][f] = 0.f;

    const int nTiles = (valid + 63) >> 6;

    {
        cp16(skb + off0, Kb + gm0); cp16(skb + off1, Kb + gm1);
        cp16(svb + off0, Vb + gm0); cp16(svb + off1, Vb + gm1);
        CP_COMMIT();
    }

    for (int tt = 0; tt < nTiles; tt++) {
        const int buf = tt & 1;
        const uint32_t bofs = (uint32_t)buf << 13;

        CP_WAIT0();
        __syncthreads();

        if (tt + 1 < nTiles) {
            const uint32_t ob = (uint32_t)(buf ^ 1) << 13;
            const __half* Kt = Kb + (size_t)(tt + 1) * 64 * 64;
            const __half* Vt = Vb + (size_t)(tt + 1) * 64 * 64;
            cp16(skb + ob + off0, Kt + gm0); cp16(skb + ob + off1, Kt + gm1);
            cp16(svb + ob + off0, Vt + gm0); cp16(svb + ob + off1, Vt + gm1);
            CP_COMMIT();
        }

        const int kbase = tt << 6;

        float sc[8][4];
#pragma unroll
        for (int nf = 0; nf < 8; nf++)
#pragma unroll
            for (int f = 0; f < 4; f++) sc[nf][f] = 0.f;

#pragma unroll
        for (int ks = 0; ks < 4; ks++) {
            const uint32_t koff = (((uint32_t)ks << 5) | k_cbit) ^ xr;
#pragma unroll
            for (int nfp = 0; nfp < 4; nfp++) {
                uint32_t r[4];
                ldsm_x4(r, k_rowbase + bofs + ((uint32_t)nfp << 11) + koff);
                mma_f16_16x8x16(sc[2 * nfp    ], qf[ks], r    );
                mma_f16_16x8x16(sc[2 * nfp + 1], qf[ks], r + 2);
            }
        }

        if (kbase + 64 > valid) {
#pragma unroll
            for (int nf = 0; nf < 8; nf++) {
                const int c0 = kbase + nf * 8 + 2 * t;
                if (c0     >= valid) { sc[nf][0] = -1e30f; sc[nf][2] = -1e30f; }
                if (c0 + 1 >= valid) { sc[nf][1] = -1e30f; sc[nf][3] = -1e30f; }
            }
        }

        float mx0 = -1e30f, mx1 = -1e30f;
#pragma unroll
        for (int nf = 0; nf < 8; nf++) {
            mx0 = fmaxf(mx0, fmaxf(sc[nf][0], sc[nf][1]));
            mx1 = fmaxf(mx1, fmaxf(sc[nf][2], sc[nf][3]));
        }
        mx0 = fmaxf(mx0, __shfl_xor_sync(0xffffffffu, mx0, 1));
        mx0 = fmaxf(mx0, __shfl_xor_sync(0xffffffffu, mx0, 2));
        mx1 = fmaxf(mx1, __shfl_xor_sync(0xffffffffu, mx1, 1));
        mx1 = fmaxf(mx1, __shfl_xor_sync(0xffffffffu, mx1, 2));

        const float m0n = fmaxf(m0, mx0);
        const float m1n = fmaxf(m1, mx1);
        const float s0  = ex2(m0 - m0n);
        const float s1  = ex2(m1 - m1n);
        m0 = m0n; m1 = m1n;

        uint32_t pf[8][2];
        float l0a = 0.f, l1a = 0.f;
#pragma unroll
        for (int nf = 0; nf < 8; nf++) {
            const float p0 = ex2(sc[nf][0] - m0n);
            const float p1 = ex2(sc[nf][1] - m0n);
            const float p2 = ex2(sc[nf][2] - m1n);
            const float p3 = ex2(sc[nf][3] - m1n);
            l0a += p0 + p1;  l1a += p2 + p3;
            pf[nf][0] = h2u(__floats2half2_rn(p0, p1));
            pf[nf][1] = h2u(__floats2half2_rn(p2, p3));
        }
        l0 = l0 * s0 + l0a;
        l1 = l1 * s1 + l1a;
#pragma unroll
        for (int nf = 0; nf < 8; nf++) {
            o[nf][0] *= s0; o[nf][1] *= s0;
            o[nf][2] *= s1; o[nf][3] *= s1;
        }

#pragma unroll
        for (int ks = 0; ks < 4; ks++) {
            uint32_t af[4];
            af[0] = pf[2 * ks][0];
            af[1] = pf[2 * ks][1];
            af[2] = pf[2 * ks + 1][0];
            af[3] = pf[2 * ks + 1][1];
            const uint32_t vrow = v_rowbase + bofs + ((uint32_t)ks << 11);
#pragma unroll
            for (int nfp = 0; nfp < 4; nfp++) {
                uint32_t r[4];
                ldsm_x4_trans(r, vrow + ((((uint32_t)nfp << 5) + v_cbit) ^ xr));
                mma_f16_16x8x16(o[2 * nfp    ], af, r    );
                mma_f16_16x8x16(o[2 * nfp + 1], af, r + 2);
            }
        }
    }

    l0 += __shfl_xor_sync(0xffffffffu, l0, 1);
    l0 += __shfl_xor_sync(0xffffffffu, l0, 2);
    l1 += __shfl_xor_sync(0xffffffffu, l1, 1);
    l1 += __shfl_xor_sync(0xffffffffu, l1, 2);
    const float i0 = 1.f / l0;
    const float i1 = 1.f / l1;

    const int row0 = q0 + wr * 16 + g;
    __half* out0 = ctx + ((size_t)b * SEQQ + row0) * DMODEL + h * DHEAD;
    __half* out1 = out0 + (size_t)8 * DMODEL;
#pragma unroll
    for (int nf = 0; nf < 8; nf++) {
        const int col = nf * 8 + 2 * t;
        *(__half2*)(out0 + col) = __floats2half2_rn(o[nf][0] * i0, o[nf][1] * i0);
        *(__half2*)(out1 + col) = __floats2half2_rn(o[nf][2] * i1, o[nf][3] * i1);
    }
}

// =====================================================================
// launch
// =====================================================================
extern "C" void kernel_launch(void* const* d_in, const int* in_sizes, int n_in,
                              void* d_out, int out_size)
{
    const float* queries    = (const float*)d_in[0];
    const float* keys       = (const float*)d_in[1];
    const float* values     = (const float*)d_in[2];
    const int*   valid_lens = (const int*)  d_in[3];
    const float* W_q        = (const float*)d_in[4];
    const float* W_k        = (const float*)d_in[5];
    const float* W_v        = (const float*)d_in[6];
    const float* W_o        = (const float*)d_in[7];

    void *qp, *kp, *vp, *ctx;
    cudaGetSymbolAddress(&qp,  g_qph);
    cudaGetSymbolAddress(&kp,  g_kph);
    cudaGetSymbolAddress(&vp,  g_vph);
    cudaGetSymbolAddress(&ctx, g_ctxh);

    // pre-convert weights + inputs to fp16 (QSCALE folded into W_q)
    dim3 gw(DMODEL * DMODEL / 2048, 4);            // (128, 4)
    cvt_w<<<gw, 256>>>(W_q, W_k, W_v, W_o);
    dim3 gx((size_t)BATCH * SEQQ * DMODEL / 2048, 3);  // (2048, 3)
    cvt_x<<<gx, 256>>>(queries, keys, values);

    dim3 gridQKV(DMODEL / 128, (BATCH * SEQQ) / 128, 3);   // (4, 64, 3)
    gemm_qkv<<<gridQKV, 256>>>((__half*)qp, (__half*)kp, (__half*)vp);

    dim3 gridF(SEQQ / 128, NBH);                           // (16, 32)
    flash_attn<<<gridF, 256>>>(valid_lens, (__half*)ctx);

    dim3 gridO(DMODEL / 128, (BATCH * SEQQ) / 128);        // (4, 64)
    gemm_out<<<gridO, 256>>>((const __half*)ctx, (float*)d_out);
}

// round 15
// speedup vs baseline: 11.2753x; 1.0800x over previous
#include <cuda_runtime.h>
#include <cuda_fp16.h>
#include <cstdint>

#define BATCH  4
#define SEQQ   2048
#define SEQK   2048
#define DMODEL 512
#define NH     8
#define DHEAD  64
#define NBH    (BATCH*NH)

// Q prescale: 1/sqrt(64) * log2(e)  (softmax runs in exp2 domain)
#define QSCALE 0.18033688011112042f

// ---------------- scratch (static device globals; no allocation) ----------------
__device__ __align__(16) __half g_qph[ (size_t)NBH*SEQQ*DHEAD ];   // [B,H,S,DH] fp16 (prescaled)
__device__ __align__(16) __half g_kph[ (size_t)NBH*SEQK*DHEAD ];
__device__ __align__(16) __half g_vph[ (size_t)NBH*SEQK*DHEAD ];
__device__ __align__(16) __half g_ctxh[ (size_t)BATCH*SEQQ*DMODEL ]; // [B,Q,D] fp16
__device__ __align__(16) __half g_wh [ (size_t)4*DMODEL*DMODEL ];    // fp16 weights (Wq*QSCALE, Wk, Wv, Wo)
__device__ __align__(16) __half g_xh [ (size_t)3*BATCH*SEQQ*DMODEL ];// fp16 inputs (q,k,v)

// =====================================================================
// helpers (sm_80+ path; compiles on compute_103)
// =====================================================================
__device__ __forceinline__ void mma_f16_16x8x16(float* d, const uint32_t* a,
                                                const uint32_t* b) {
    asm volatile(
        "mma.sync.aligned.m16n8k16.row.col.f32.f16.f16.f32 "
        "{%0,%1,%2,%3}, {%4,%5,%6,%7}, {%8,%9}, {%0,%1,%2,%3};"
        : "+f"(d[0]), "+f"(d[1]), "+f"(d[2]), "+f"(d[3])
        : "r"(a[0]), "r"(a[1]), "r"(a[2]), "r"(a[3]), "r"(b[0]), "r"(b[1]));
}

__device__ __forceinline__ void ldsm_x4(uint32_t* r, uint32_t addr) {
    asm volatile("ldmatrix.sync.aligned.m8n8.x4.shared.b16 {%0,%1,%2,%3}, [%4];"
                 : "=r"(r[0]), "=r"(r[1]), "=r"(r[2]), "=r"(r[3]) : "r"(addr));
}
__device__ __forceinline__ void ldsm_x4_trans(uint32_t* r, uint32_t addr) {
    asm volatile("ldmatrix.sync.aligned.m8n8.x4.trans.shared.b16 {%0,%1,%2,%3}, [%4];"
                 : "=r"(r[0]), "=r"(r[1]), "=r"(r[2]), "=r"(r[3]) : "r"(addr));
}

__device__ __forceinline__ uint32_t smem_u32(const void* p) {
    uint32_t a;
    asm("{ .reg .u64 t; cvta.to.shared.u64 t, %1; cvt.u32.u64 %0, t; }" : "=r"(a) : "l"(p));
    return a;
}

__device__ __forceinline__ uint32_t h2u(__half2 h) {
    return *reinterpret_cast<uint32_t*>(&h);
}

__device__ __forceinline__ float ex2(float x) {
    float y;
    asm("ex2.approx.ftz.f32 %0, %1;" : "=f"(y) : "f"(x));
    return y;
}
// packed fp16 exp2 on a half2 register
__device__ __forceinline__ uint32_t ex2_h2(uint32_t x) {
    asm("ex2.approx.f16x2 %0, %0;" : "+r"(x));
    return x;
}

__device__ __forceinline__ void cp16(uint32_t dst, const void* src) {
    asm volatile("cp.async.cg.shared.global [%0], [%1], 16;" :: "r"(dst), "l"(src));
}
#define CP_COMMIT() asm volatile("cp.async.commit_group;" ::: "memory")
#define CP_WAIT0()  asm volatile("cp.async.wait_group 0;"  ::: "memory")
#define CP_WAIT1()  asm volatile("cp.async.wait_group 1;"  ::: "memory")

// =====================================================================
// fp32 -> fp16 converter (weights + inputs, one launch)
// blockIdx.y: 0..3 weights (Wq scaled), 4..6 inputs.
// =====================================================================
__global__ __launch_bounds__(256)
void cvt_all(const float* __restrict__ Xq, const float* __restrict__ Xk,
             const float* __restrict__ Xv,
             const float* __restrict__ Wq, const float* __restrict__ Wk,
             const float* __restrict__ Wv, const float* __restrict__ Wo)
{
    const int z = blockIdx.y;
    const float* src; __half* dst; float scale = 1.f;
    if (z < 4) {
        if (blockIdx.x >= DMODEL * DMODEL / 2048) return;
        src = (z == 0) ? Wq : (z == 1) ? Wk : (z == 2) ? Wv : Wo;
        if (z == 0) scale = QSCALE;
        dst = g_wh + (size_t)z * DMODEL * DMODEL;
    } else {
        src = (z == 4) ? Xq : (z == 5) ? Xk : Xv;
        dst = g_xh + (size_t)(z - 4) * BATCH * SEQQ * DMODEL;
    }
    const size_t i = ((size_t)blockIdx.x * 256 + threadIdx.x) * 8;
    float4 x = *(const float4*)(src + i);
    float4 y = *(const float4*)(src + i + 4);
    uint4 u;
    u.x = h2u(__floats2half2_rn(x.x * scale, x.y * scale));
    u.y = h2u(__floats2half2_rn(x.z * scale, x.w * scale));
    u.z = h2u(__floats2half2_rn(y.x * scale, y.y * scale));
    u.w = h2u(__floats2half2_rn(y.z * scale, y.w * scale));
    *(uint4*)(dst + i) = u;
}

// =====================================================================
// all-fp16 HMMA GEMM: C[M,512] = A[M,512] @ W[N,512]^T
// 128x128 block tile, 8 warps (2x4), warp tile 64x32.
// BK=32 chunks, 3-stage cp.async pipeline (wait_group 1; chunk ch
// computes while ch+1 and ch+2 load). smem 48 KB static.
// HOUT=1: fp16 scatter to [B,H,S,DH]; HOUT=0: fp32 [M,N].
// =====================================================================
template<int HOUT>
__device__ __forceinline__ void gemm_h_body(const __half* __restrict__ A,
                                            const __half* __restrict__ W,
                                            void* __restrict__ Cv)
{
    __shared__ __align__(16) __half sA[3][128 * 32];   // 3 x 8 KB
    __shared__ __align__(16) __half sB[3][128 * 32];   // 3 x 8 KB

    const int tid  = threadIdx.x;
    const int wid  = tid >> 5;
    const int lane = tid & 31;
    const int m0   = blockIdx.y * 128;
    const int n0   = blockIdx.x * 128;

    const int warp_m = wid >> 2;
    const int warp_n = wid & 3;
    const int g  = lane >> 2;
    const int t  = lane & 3;
    const int mm = lane >> 3;
    const int r8 = lane & 7;

    const uint32_t sAb = smem_u32(sA);
    const uint32_t sBb = smem_u32(sB);
    const uint32_t axor = (uint32_t)((r8 >> 1) & 3);
    const uint32_t a_base = sAb + (uint32_t)(warp_m * 64 + ((mm & 1) << 3) + r8) * 64;
    const uint32_t b_base = sBb + (uint32_t)(warp_n * 32 + ((mm >> 1) << 3) + r8) * 64;

    const int row0 = tid >> 2,           c0 = tid & 3;
    const int row1 = (tid + 256) >> 2,   c1 = (tid + 256) & 3;
    const uint32_t d0 = (uint32_t)(row0 * 64 + (((uint32_t)c0 ^ ((row0 >> 1) & 3)) << 4));
    const uint32_t d1 = (uint32_t)(row1 * 64 + (((uint32_t)c1 ^ ((row1 >> 1) & 3)) << 4));
    const __half* Ag0 = A + (size_t)(m0 + row0) * DMODEL + c0 * 8;
    const __half* Ag1 = A + (size_t)(m0 + row1) * DMODEL + c1 * 8;
    const __half* Wg0 = W + (size_t)(n0 + row0) * DMODEL + c0 * 8;
    const __half* Wg1 = W + (size_t)(n0 + row1) * DMODEL + c1 * 8;

    float acc[4][4][4];
#pragma unroll
    for (int mi = 0; mi < 4; mi++)
#pragma unroll
        for (int ni = 0; ni < 4; ni++)
#pragma unroll
            for (int f = 0; f < 4; f++) acc[mi][ni][f] = 0.f;

    // prologue: stage chunks 0,1 into buffers 0,1
#pragma unroll
    for (int p = 0; p < 2; p++) {
        const uint32_t ob = (uint32_t)p * 8192;
        const int kk = p << 5;
        cp16(sAb + ob + d0, Ag0 + kk); cp16(sAb + ob + d1, Ag1 + kk);
        cp16(sBb + ob + d0, Wg0 + kk); cp16(sBb + ob + d1, Wg1 + kk);
        CP_COMMIT();
    }

    for (int ch = 0; ch < 16; ++ch) {
        const uint32_t bofs = (uint32_t)(ch % 3) * 8192;

        CP_WAIT1();          // chunk ch landed (ch+1 may still be in flight)
        __syncthreads();

        if (ch + 2 < 16) {
            const uint32_t ob = (uint32_t)((ch + 2) % 3) * 8192;
            const int kk = (ch + 2) << 5;
            cp16(sAb + ob + d0, Ag0 + kk); cp16(sAb + ob + d1, Ag1 + kk);
            cp16(sBb + ob + d0, Wg0 + kk); cp16(sBb + ob + d1, Wg1 + kk);
        }
        CP_COMMIT();         // always commit (empty groups keep the count in step)

#pragma unroll
        for (int ks = 0; ks < 2; ks++) {
            uint32_t af[4][4];
            const uint32_t ac = ((((uint32_t)(ks << 1) | (uint32_t)(mm >> 1)) ^ axor) << 4);
#pragma unroll
            for (int mi = 0; mi < 4; mi++)
                ldsm_x4(af[mi], a_base + bofs + ((uint32_t)mi << 10) + ac);
            uint32_t bf[2][4];
            const uint32_t bc = ((((uint32_t)(ks << 1) | (uint32_t)(mm & 1)) ^ axor) << 4);
#pragma unroll
            for (int nfp = 0; nfp < 2; nfp++)
                ldsm_x4(bf[nfp], b_base + bofs + ((uint32_t)nfp << 10) + bc);
#pragma unroll
            for (int mi = 0; mi < 4; mi++)
#pragma unroll
                for (int nfp = 0; nfp < 2; nfp++) {
                    mma_f16_16x8x16(acc[mi][2 * nfp    ], af[mi], bf[nfp]    );
                    mma_f16_16x8x16(acc[mi][2 * nfp + 1], af[mi], bf[nfp] + 2);
                }
        }
    }

#pragma unroll
    for (int mi = 0; mi < 4; mi++) {
#pragma unroll
        for (int ni = 0; ni < 4; ni++) {
            const int row = m0 + warp_m * 64 + mi * 16 + g;
            const int col = n0 + warp_n * 32 + ni * 8 + t * 2;
            if (HOUT) {
                __half* Ch = (__half*)Cv;
                const int b = row >> 11, s = row & 2047;
                const int hh = col >> 6, dh = col & 63;
                size_t o0 = ((((size_t)b * NH + hh) * SEQQ + s) << 6) + dh;
                *(__half2*)(Ch + o0) =
                    __floats2half2_rn(acc[mi][ni][0], acc[mi][ni][1]);
                *(__half2*)(Ch + o0 + ((size_t)8 << 6)) =
                    __floats2half2_rn(acc[mi][ni][2], acc[mi][ni][3]);
            } else {
                float* Cf = (float*)Cv;
                size_t o0 = (size_t)row * DMODEL + col;
                *(float2*)(Cf + o0) = make_float2(acc[mi][ni][0], acc[mi][ni][1]);
                *(float2*)(Cf + o0 + (size_t)8 * DMODEL) =
                    make_float2(acc[mi][ni][2], acc[mi][ni][3]);
            }
        }
    }
}

// Fused Q/K/V projections (blockIdx.z selects GEMM).
__global__ __launch_bounds__(256, 2)
void gemm_qkv(__half* __restrict__ Cq, __half* __restrict__ Ck,
              __half* __restrict__ Cv)
{
    const int z = blockIdx.z;
    const __half* A = g_xh + (size_t)z * BATCH * SEQQ * DMODEL;
    const __half* W = g_wh + (size_t)z * DMODEL * DMODEL;
    __half* C = (z == 0) ? Cq : (z == 1) ? Ck : Cv;
    gemm_h_body<1>(A, W, C);
}

__global__ __launch_bounds__(256, 2)
void gemm_out(const __half* __restrict__ ctx, float* __restrict__ out)
{
    gemm_h_body<0>(ctx, g_wh + (size_t)3 * DMODEL * DMODEL, out);
}

// =====================================================================
// Flash attention: fp16 mma + ldmatrix + cp.async double-buffered K/V.
// Softmax: exp2 in packed fp16 (ex2.approx.f16x2); l via ones-MMA
// (fp32, consistent with the P actually fed to PV; no epilogue shfl).
// =====================================================================
__global__ __launch_bounds__(256, 2)
void flash_attn(const int* __restrict__ valid_lens, __half* __restrict__ ctx)
{
    __shared__ __align__(16) __half sK[2][64 * 64];   // 2 x 8 KB
    __shared__ __align__(16) __half sV[2][64 * 64];   // 2 x 8 KB

    const int tid  = threadIdx.x;
    const int wr   = tid >> 5;
    const int lane = tid & 31;
    const int g    = lane >> 2;
    const int t    = lane & 3;

    const int bh = blockIdx.y;
    const int b  = bh >> 3;
    const int h  = bh & 7;
    const int q0 = blockIdx.x << 7;     // BQ = 128
    const int valid = valid_lens[b];

    const __half* Qw = g_qph + ((size_t)bh * SEQQ + q0 + wr * 16) * DHEAD;
    const __half* Kb = g_kph + (size_t)bh * SEQK * DHEAD;
    const __half* Vb = g_vph + (size_t)bh * SEQK * DHEAD;

    uint32_t qf[4][4];
#pragma unroll
    for (int j = 0; j < 4; j++) {
        qf[j][0] = *(const uint32_t*)(Qw + (g    ) * 64 + j * 16 + 2 * t);
        qf[j][1] = *(const uint32_t*)(Qw + (g + 8) * 64 + j * 16 + 2 * t);
        qf[j][2] = *(const uint32_t*)(Qw + (g    ) * 64 + j * 16 + 8 + 2 * t);
        qf[j][3] = *(const uint32_t*)(Qw + (g + 8) * 64 + j * 16 + 8 + 2 * t);
    }

    const int k0s = tid >> 3,         c0s = tid & 7;
    const int k1s = (tid + 256) >> 3, c1s = (tid + 256) & 7;
    const uint32_t off0 = (uint32_t)(k0s * 128 + (((uint32_t)c0s << 4) ^ ((k0s & 7) << 4)));
    const uint32_t off1 = (uint32_t)(k1s * 128 + (((uint32_t)c1s << 4) ^ ((k1s & 7) << 4)));
    const size_t gm0 = (size_t)k0s * 64 + c0s * 8;
    const size_t gm1 = (size_t)k1s * 64 + c1s * 8;

    const uint32_t skb = smem_u32(sK);
    const uint32_t svb = smem_u32(sV);
    const int m  = lane >> 3;
    const int r8 = lane & 7;
    const uint32_t xr = (uint32_t)r8 << 4;
    const uint32_t k_rowbase = skb + (uint32_t)(((m >> 1) << 3) + r8) * 128;
    const uint32_t k_cbit    = (uint32_t)(m & 1) << 4;
    const uint32_t v_rowbase = svb + (uint32_t)(((m & 1) << 3) + r8) * 128;
    const uint32_t v_cbit    = (uint32_t)(m >> 1) << 4;

    const uint32_t ones2 = 0x3C003C00u;           // half2(1,1)
    const uint32_t onesfrag[2] = { ones2, ones2 };

    float m0 = -1e30f, m1 = -1e30f;
    float l_acc[4] = {0.f, 0.f, 0.f, 0.f};        // l via ones-MMA (cols identical)
    float o[8][4];
#pragma unroll
    for (int nf = 0; nf < 8; nf++)
#pragma unroll
        for (int f = 0; f < 4; f++) o[nf][f] = 0.f;

    const int nTiles = (valid + 63) >> 6;

    {
        cp16(skb + off0, Kb + gm0); cp16(skb + off1, Kb + gm1);
        cp16(svb + off0, Vb + gm0); cp16(svb + off1, Vb + gm1);
        CP_COMMIT();
    }

    for (int tt = 0; tt < nTiles; tt++) {
        const int buf = tt & 1;
        const uint32_t bofs = (uint32_t)buf << 13;

        CP_WAIT0();
        __syncthreads();

        if (tt + 1 < nTiles) {
            const uint32_t ob = (uint32_t)(buf ^ 1) << 13;
            const __half* Kt = Kb + (size_t)(tt + 1) * 64 * 64;
            const __half* Vt = Vb + (size_t)(tt + 1) * 64 * 64;
            cp16(skb + ob + off0, Kt + gm0); cp16(skb + ob + off1, Kt + gm1);
            cp16(svb + ob + off0, Vt + gm0); cp16(svb + ob + off1, Vt + gm1);
            CP_COMMIT();
        }

        const int kbase = tt << 6;

        // ---- S = Q K^T (log2-scaled) ----
        float sc[8][4];
#pragma unroll
        for (int nf = 0; nf < 8; nf++)
#pragma unroll
            for (int f = 0; f < 4; f++) sc[nf][f] = 0.f;

#pragma unroll
        for (int ks = 0; ks < 4; ks++) {
            const uint32_t koff = (((uint32_t)ks << 5) | k_cbit) ^ xr;
#pragma unroll
            for (int nfp = 0; nfp < 4; nfp++) {
                uint32_t r[4];
                ldsm_x4(r, k_rowbase + bofs + ((uint32_t)nfp << 11) + koff);
                mma_f16_16x8x16(sc[2 * nfp    ], qf[ks], r    );
                mma_f16_16x8x16(sc[2 * nfp + 1], qf[ks], r + 2);
            }
        }

        // ---- mask tail columns ----
        if (kbase + 64 > valid) {
#pragma unroll
            for (int nf = 0; nf < 8; nf++) {
                const int c0 = kbase + nf * 8 + 2 * t;
                if (c0     >= valid) { sc[nf][0] = -1e30f; sc[nf][2] = -1e30f; }
                if (c0 + 1 >= valid) { sc[nf][1] = -1e30f; sc[nf][3] = -1e30f; }
            }
        }

        // ---- online softmax (packed fp16 exp2) ----
        float mx0 = -1e30f, mx1 = -1e30f;
#pragma unroll
        for (int nf = 0; nf < 8; nf++) {
            mx0 = fmaxf(mx0, fmaxf(sc[nf][0], sc[nf][1]));
            mx1 = fmaxf(mx1, fmaxf(sc[nf][2], sc[nf][3]));
        }
        mx0 = fmaxf(mx0, __shfl_xor_sync(0xffffffffu, mx0, 1));
        mx0 = fmaxf(mx0, __shfl_xor_sync(0xffffffffu, mx0, 2));
        mx1 = fmaxf(mx1, __shfl_xor_sync(0xffffffffu, mx1, 1));
        mx1 = fmaxf(mx1, __shfl_xor_sync(0xffffffffu, mx1, 2));

        const float m0n = fmaxf(m0, mx0);
        const float m1n = fmaxf(m1, mx1);
        const float s0  = ex2(m0 - m0n);
        const float s1  = ex2(m1 - m1n);
        m0 = m0n; m1 = m1n;

        uint32_t pf[8][2];
#pragma unroll
        for (int nf = 0; nf < 8; nf++) {
            pf[nf][0] = ex2_h2(h2u(__floats2half2_rn(sc[nf][0] - m0n, sc[nf][1] - m0n)));
            pf[nf][1] = ex2_h2(h2u(__floats2half2_rn(sc[nf][2] - m1n, sc[nf][3] - m1n)));
        }
        l_acc[0] *= s0; l_acc[1] *= s0; l_acc[2] *= s1; l_acc[3] *= s1;
#pragma unroll
        for (int nf = 0; nf < 8; nf++) {
            o[nf][0] *= s0; o[nf][1] *= s0;
            o[nf][2] *= s1; o[nf][3] *= s1;
        }

        // ---- O += P V ; l += P 1 ----
#pragma unroll
        for (int ks = 0; ks < 4; ks++) {
            uint32_t af[4];
            af[0] = pf[2 * ks][0];
            af[1] = pf[2 * ks][1];
            af[2] = pf[2 * ks + 1][0];
            af[3] = pf[2 * ks + 1][1];
            mma_f16_16x8x16(l_acc, af, onesfrag);
            const uint32_t vrow = v_rowbase + bofs + ((uint32_t)ks << 11);
#pragma unroll
            for (int nfp = 0; nfp < 4; nfp++) {
                uint32_t r[4];
                ldsm_x4_trans(r, vrow + ((((uint32_t)nfp << 5) + v_cbit) ^ xr));
                mma_f16_16x8x16(o[2 * nfp    ], af, r    );
                mma_f16_16x8x16(o[2 * nfp + 1], af, r + 2);
            }
        }
    }

    // ---- epilogue (l already row-complete; no shfl needed) ----
    const float i0 = 1.f / l_acc[0];
    const float i1 = 1.f / l_acc[2];

    const int row0 = q0 + wr * 16 + g;
    __half* out0 = ctx + ((size_t)b * SEQQ + row0) * DMODEL + h * DHEAD;
    __half* out1 = out0 + (size_t)8 * DMODEL;
#pragma unroll
    for (int nf = 0; nf < 8; nf++) {
        const int col = nf * 8 + 2 * t;
        *(__half2*)(out0 + col) = __floats2half2_rn(o[nf][0] * i0, o[nf][1] * i0);
        *(__half2*)(out1 + col) = __floats2half2_rn(o[nf][2] * i1, o[nf][3] * i1);
    }
}

// =====================================================================
// launch
// =====================================================================
extern "C" void kernel_launch(void* const* d_in, const int* in_sizes, int n_in,
                              void* d_out, int out_size)
{
    const float* queries    = (const float*)d_in[0];
    const float* keys       = (const float*)d_in[1];
    const float* values     = (const float*)d_in[2];
    const int*   valid_lens = (const int*)  d_in[3];
    const float* W_q        = (const float*)d_in[4];
    const float* W_k        = (const float*)d_in[5];
    const float* W_v        = (const float*)d_in[6];
    const float* W_o        = (const float*)d_in[7];

    void *qp, *kp, *vp, *ctx;
    cudaGetSymbolAddress(&qp,  g_qph);
    cudaGetSymbolAddress(&kp,  g_kph);
    cudaGetSymbolAddress(&vp,  g_vph);
    cudaGetSymbolAddress(&ctx, g_ctxh);

    // pre-convert weights + inputs to fp16 (QSCALE folded into W_q), one launch
    dim3 gc((size_t)BATCH * SEQQ * DMODEL / 2048, 7);   // (2048, 7)
    cvt_all<<<gc, 256>>>(queries, keys, values, W_q, W_k, W_v, W_o);

    dim3 gridQKV(DMODEL / 128, (BATCH * SEQQ) / 128, 3);   // (4, 64, 3)
    gemm_qkv<<<gridQKV, 256>>>((__half*)qp, (__half*)kp, (__half*)vp);

    dim3 gridF(SEQQ / 128, NBH);                           // (16, 32)
    flash_attn<<<gridF, 256>>>(valid_lens, (__half*)ctx);

    dim3 gridO(DMODEL / 128, (BATCH * SEQQ) / 128);        // (4, 64)
    gemm_out<<<gridO, 256>>>((const __half*)ctx, (float*)d_out);
}